// round 1
// baseline (speedup 1.0000x reference)
#include <cuda_runtime.h>
#include <cuda_bf16.h>
#include <math.h>

// Problem constants
#define CB 4
#define CT 4096
#define CD 1024
#define CH 16
#define CK 64
#define CF 4096
#define CN (CB*CT)          // 16384 tokens

#define LN_EPS  1e-5f
#define DEN_EPS 1e-6f

// ---------------------------------------------------------------------------
// Scratch (allocation-free: __device__ globals)
// ---------------------------------------------------------------------------
__device__ float g_xn  [(size_t)CN*CD];
__device__ float g_q   [(size_t)CN*CD];
__device__ float g_k   [(size_t)CN*CD];
__device__ float g_v   [(size_t)CN*CD];
__device__ float g_attn[(size_t)CN*CD];
__device__ float g_x2  [(size_t)CN*CD];
__device__ float g_y   [(size_t)CN*CD];
__device__ float g_h   [(size_t)CN*CF];
__device__ float g_kv  [CB*CH*CK*CK];
__device__ float g_ksum[CB*CH*CK];

// ---------------------------------------------------------------------------
// LayerNorm: one block per row (1024 elems), 256 threads x float4
// ---------------------------------------------------------------------------
__device__ __forceinline__ float block_sum_256(float v, float* red) {
    #pragma unroll
    for (int o = 16; o > 0; o >>= 1) v += __shfl_xor_sync(0xffffffffu, v, o);
    if ((threadIdx.x & 31) == 0) red[threadIdx.x >> 5] = v;
    __syncthreads();
    if (threadIdx.x < 32) {
        float t = (threadIdx.x < 8) ? red[threadIdx.x] : 0.f;
        #pragma unroll
        for (int o = 4; o > 0; o >>= 1) t += __shfl_xor_sync(0xffffffffu, t, o);
        if (threadIdx.x == 0) red[8] = t;
    }
    __syncthreads();
    return red[8];
}

__global__ void ln_kernel(const float* __restrict__ x,
                          const float* __restrict__ w,
                          const float* __restrict__ b,
                          float* __restrict__ y)
{
    __shared__ float red[9];
    int row = blockIdx.x;
    int tid = threadIdx.x;
    const float4* xr = reinterpret_cast<const float4*>(x + (size_t)row * CD);
    float4 v = xr[tid];

    float s = v.x + v.y + v.z + v.w;
    float mean = block_sum_256(s, red) * (1.f / CD);

    float dx = v.x - mean, dy = v.y - mean, dz = v.z - mean, dw = v.w - mean;
    float s2 = dx*dx + dy*dy + dz*dz + dw*dw;
    float var = block_sum_256(s2, red) * (1.f / CD);
    float rs = rsqrtf(var + LN_EPS);

    float4 wv = reinterpret_cast<const float4*>(w)[tid];
    float4 bv = reinterpret_cast<const float4*>(b)[tid];
    float4 o;
    o.x = dx * rs * wv.x + bv.x;
    o.y = dy * rs * wv.y + bv.y;
    o.z = dz * rs * wv.z + bv.z;
    o.w = dw * rs * wv.w + bv.w;
    reinterpret_cast<float4*>(y + (size_t)row * CD)[tid] = o;
}

// ---------------------------------------------------------------------------
// Tiled fp32 GEMM: C[N,M] = A[N,Kd] @ W[Kd,M] + bias (+ epilogue)
// BM=BN=128, BK=16, 256 threads, 8x8 per-thread microtile
// epi: 0=none, 1=phi(elu+1), 2=gelu(exact), 3=+res
// ---------------------------------------------------------------------------
#define GBM 128
#define GBN 128
#define GBK 16
#define GAS 132   // padded row length for As

__global__ __launch_bounds__(256) void gemm_kernel(
    const float* __restrict__ A, const float* __restrict__ W,
    const float* __restrict__ bias, const float* __restrict__ res,
    float* __restrict__ C, int M, int Kd, int epi)
{
    __shared__ float As[GBK][GAS];
    __shared__ float Bs[GBK][GBN];

    int tid = threadIdx.x;
    int bm = blockIdx.y * GBM;
    int bn = blockIdx.x * GBN;
    int tx = tid & 15, ty = tid >> 4;

    const float* Aptr = A + (size_t)bm * Kd;
    const float* Wptr = W + bn;

    float acc[8][8];
    #pragma unroll
    for (int i = 0; i < 8; i++)
        #pragma unroll
        for (int j = 0; j < 8; j++) acc[i][j] = 0.f;

    for (int k0 = 0; k0 < Kd; k0 += GBK) {
        // Load A tile (128x16) transposed into As[k][m]
        #pragma unroll
        for (int i = 0; i < 2; i++) {
            int f = tid + i * 256;          // 0..511 float4 slots
            int r = f >> 2;                 // 0..127
            int cv = (f & 3) << 2;          // 0,4,8,12
            float4 a = *reinterpret_cast<const float4*>(Aptr + (size_t)r * Kd + k0 + cv);
            As[cv + 0][r] = a.x;
            As[cv + 1][r] = a.y;
            As[cv + 2][r] = a.z;
            As[cv + 3][r] = a.w;
        }
        // Load B tile (16x128)
        #pragma unroll
        for (int i = 0; i < 2; i++) {
            int f = tid + i * 256;
            int r = f >> 5;                 // 0..15
            int c = (f & 31) << 2;          // 0..124
            float4 bvec = *reinterpret_cast<const float4*>(Wptr + (size_t)(k0 + r) * M + c);
            *reinterpret_cast<float4*>(&Bs[r][c]) = bvec;
        }
        __syncthreads();

        #pragma unroll
        for (int k = 0; k < GBK; k++) {
            float am[8], bn_[8];
            float4 a0 = *reinterpret_cast<const float4*>(&As[k][ty * 8]);
            float4 a1 = *reinterpret_cast<const float4*>(&As[k][ty * 8 + 4]);
            float4 b0 = *reinterpret_cast<const float4*>(&Bs[k][tx * 8]);
            float4 b1 = *reinterpret_cast<const float4*>(&Bs[k][tx * 8 + 4]);
            am[0]=a0.x; am[1]=a0.y; am[2]=a0.z; am[3]=a0.w;
            am[4]=a1.x; am[5]=a1.y; am[6]=a1.z; am[7]=a1.w;
            bn_[0]=b0.x; bn_[1]=b0.y; bn_[2]=b0.z; bn_[3]=b0.w;
            bn_[4]=b1.x; bn_[5]=b1.y; bn_[6]=b1.z; bn_[7]=b1.w;
            #pragma unroll
            for (int i = 0; i < 8; i++)
                #pragma unroll
                for (int j = 0; j < 8; j++)
                    acc[i][j] += am[i] * bn_[j];
        }
        __syncthreads();
    }

    // Epilogue
    #pragma unroll
    for (int i = 0; i < 8; i++) {
        int row = bm + ty * 8 + i;
        #pragma unroll
        for (int j = 0; j < 8; j++) {
            int col = bn + tx * 8 + j;
            float val = acc[i][j] + bias[col];
            if (epi == 1) {
                val = (val > 0.f) ? (val + 1.f) : expf(val);   // elu(x)+1
            } else if (epi == 2) {
                val = 0.5f * val * (1.f + erff(val * 0.7071067811865475f));
            } else if (epi == 3) {
                val += res[(size_t)row * M + col];
            }
            C[(size_t)row * M + col] = val;
        }
    }
}

// ---------------------------------------------------------------------------
// Zero a float buffer
// ---------------------------------------------------------------------------
__global__ void zero_kernel(float* p, int n) {
    int i = blockIdx.x * 256 + threadIdx.x;
    if (i < n) p[i] = 0.f;
}

// ---------------------------------------------------------------------------
// kv[bh][k][v] = sum_s keep_s * phi_k[s][k] * v[s][v]  ;  ksum[bh][k]
// grid (64 bh, 8 chunks), 256 threads, each thread owns a 4x4 kv microtile
// ---------------------------------------------------------------------------
__global__ void kv_kernel(const float* __restrict__ pk,
                          const float* __restrict__ vv,
                          const unsigned char* __restrict__ mask)
{
    __shared__ float sp[8][CK];
    __shared__ float sv[8][CK];

    int bh = blockIdx.x;           // 0..63
    int chunk = blockIdx.y;        // 0..7
    int b = bh / CH, h = bh % CH;
    int t0 = chunk * (CT / 8);     // 512 tokens per chunk

    int tid = threadIdx.x;
    int r0 = (tid >> 4) << 2;      // 0..60
    int c0 = (tid & 15) << 2;      // 0..60

    float acc[4][4];
    #pragma unroll
    for (int i = 0; i < 4; i++)
        #pragma unroll
        for (int j = 0; j < 4; j++) acc[i][j] = 0.f;
    float ks = 0.f;

    for (int g = 0; g < 512; g += 8) {
        #pragma unroll
        for (int i = 0; i < 2; i++) {
            int e = tid + i * 256;          // 0..511
            int s = e >> 6, col = e & 63;
            int t = t0 + g + s;
            size_t rowm = (size_t)b * CT + t;
            float keep = mask[rowm] ? 0.f : 1.f;
            size_t idx = rowm * CD + (size_t)h * CK + col;
            sp[s][col] = pk[idx] * keep;
            sv[s][col] = vv[idx] * keep;
        }
        __syncthreads();
        #pragma unroll
        for (int s = 0; s < 8; s++) {
            float4 a  = *reinterpret_cast<const float4*>(&sp[s][r0]);
            float4 bb = *reinterpret_cast<const float4*>(&sv[s][c0]);
            float ar[4] = {a.x, a.y, a.z, a.w};
            float br[4] = {bb.x, bb.y, bb.z, bb.w};
            #pragma unroll
            for (int i = 0; i < 4; i++)
                #pragma unroll
                for (int j = 0; j < 4; j++)
                    acc[i][j] += ar[i] * br[j];
        }
        if (tid < CK) {
            #pragma unroll
            for (int s = 0; s < 8; s++) ks += sp[s][tid];
        }
        __syncthreads();
    }

    float* kvp = g_kv + (size_t)bh * CK * CK;
    #pragma unroll
    for (int i = 0; i < 4; i++)
        #pragma unroll
        for (int j = 0; j < 4; j++)
            atomicAdd(&kvp[(r0 + i) * CK + c0 + j], acc[i][j]);
    if (tid < CK) atomicAdd(&g_ksum[bh * CK + tid], ks);
}

// ---------------------------------------------------------------------------
// attn[t][c] = (phi_q[t] . kv[:,c]) / (phi_q[t] . ksum + eps)
// grid (64 bh, 32 token-blocks of 128), 256 threads = 8 warps x 16 tokens
// ---------------------------------------------------------------------------
__global__ void attn_kernel(const float* __restrict__ pq,
                            float* __restrict__ attn)
{
    __shared__ float skv[CK][CK];
    __shared__ float sks[CK];
    __shared__ float sq[8][CK];

    int bh = blockIdx.x, tb = blockIdx.y;
    int b = bh / CH, h = bh % CH;
    int tid = threadIdx.x;

    const float* kvp = g_kv + (size_t)bh * CK * CK;
    for (int i = tid; i < CK * CK; i += 256) skv[i >> 6][i & 63] = kvp[i];
    if (tid < CK) sks[tid] = g_ksum[bh * CK + tid];
    __syncthreads();

    int w = tid >> 5, l = tid & 31;
    for (int it = 0; it < 16; it++) {
        int t = tb * 128 + w * 16 + it;
        size_t rowp = ((size_t)b * CT + t) * CD + (size_t)h * CK;
        sq[w][l]      = pq[rowp + l];
        sq[w][l + 32] = pq[rowp + l + 32];
        __syncwarp();
        float n0 = 0.f, n1 = 0.f, den = DEN_EPS;
        #pragma unroll
        for (int k = 0; k < CK; k++) {
            float qv = sq[w][k];
            n0  += qv * skv[k][l];
            n1  += qv * skv[k][l + 32];
            den += qv * sks[k];
        }
        float inv = 1.f / den;
        attn[rowp + l]      = n0 * inv;
        attn[rowp + l + 32] = n1 * inv;
        __syncwarp();
    }
}

// ---------------------------------------------------------------------------
// Host launcher
// ---------------------------------------------------------------------------
extern "C" void kernel_launch(void* const* d_in, const int* in_sizes, int n_in,
                              void* d_out, int out_size)
{
    const float* x    = (const float*)d_in[0];
    const unsigned char* mask = (const unsigned char*)d_in[1];
    const float* Wq   = (const float*)d_in[2];
    const float* bq   = (const float*)d_in[3];
    const float* Wk   = (const float*)d_in[4];
    const float* bk   = (const float*)d_in[5];
    const float* Wv   = (const float*)d_in[6];
    const float* bv   = (const float*)d_in[7];
    const float* Wo   = (const float*)d_in[8];
    const float* bo   = (const float*)d_in[9];
    const float* ln1w = (const float*)d_in[10];
    const float* ln1b = (const float*)d_in[11];
    const float* ln2w = (const float*)d_in[12];
    const float* ln2b = (const float*)d_in[13];
    const float* W1   = (const float*)d_in[14];
    const float* b1   = (const float*)d_in[15];
    const float* W2   = (const float*)d_in[16];
    const float* b2   = (const float*)d_in[17];
    float* out = (float*)d_out;

    void *pxn, *pq, *pk, *pv, *pattn, *px2, *py, *ph, *pkv, *pks;
    cudaGetSymbolAddress(&pxn, g_xn);
    cudaGetSymbolAddress(&pq, g_q);
    cudaGetSymbolAddress(&pk, g_k);
    cudaGetSymbolAddress(&pv, g_v);
    cudaGetSymbolAddress(&pattn, g_attn);
    cudaGetSymbolAddress(&px2, g_x2);
    cudaGetSymbolAddress(&py, g_y);
    cudaGetSymbolAddress(&ph, g_h);
    cudaGetSymbolAddress(&pkv, g_kv);
    cudaGetSymbolAddress(&pks, g_ksum);

    float* xn   = (float*)pxn;
    float* qb   = (float*)pq;
    float* kb   = (float*)pk;
    float* vb   = (float*)pv;
    float* atb  = (float*)pattn;
    float* x2   = (float*)px2;
    float* yb   = (float*)py;
    float* hb   = (float*)ph;
    float* kvb  = (float*)pkv;
    float* ksb  = (float*)pks;

    // 1. LN1
    ln_kernel<<<CN, 256>>>(x, ln1w, ln1b, xn);

    // 2-4. QKV projections (phi fused into Q,K)
    dim3 gD(CD / GBN, CN / GBM);
    gemm_kernel<<<gD, 256>>>(xn, Wq, bq, nullptr, qb, CD, CD, 1);
    gemm_kernel<<<gD, 256>>>(xn, Wk, bk, nullptr, kb, CD, CD, 1);
    gemm_kernel<<<gD, 256>>>(xn, Wv, bv, nullptr, vb, CD, CD, 0);

    // 5. zero kv/ksum accumulators
    zero_kernel<<<(CB*CH*CK*CK + 255) / 256, 256>>>(kvb, CB*CH*CK*CK);
    zero_kernel<<<(CB*CH*CK + 255) / 256, 256>>>(ksb, CB*CH*CK);

    // 6. kv + ksum reduction (masked)
    kv_kernel<<<dim3(CB*CH, 8), 256>>>(kb, vb, mask);

    // 7. numerator / denominator
    attn_kernel<<<dim3(CB*CH, CT / 128), 256>>>(qb, atb);

    // 8. O projection + residual
    gemm_kernel<<<gD, 256>>>(atb, Wo, bo, x, x2, CD, CD, 3);

    // 9. LN2
    ln_kernel<<<CN, 256>>>(x2, ln2w, ln2b, yb);

    // 10. FFN1 + exact GELU
    dim3 gF(CF / GBN, CN / GBM);
    gemm_kernel<<<gF, 256>>>(yb, W1, b1, nullptr, hb, CF, CD, 2);

    // 11. FFN2 + residual -> output
    gemm_kernel<<<gD, 256>>>(hb, W2, b2, x2, out, CD, CF, 3);
}

// round 2
// speedup vs baseline: 2.8920x; 2.8920x over previous
#include <cuda_runtime.h>
#include <cuda_bf16.h>
#include <math.h>

// Problem constants
#define CB 4
#define CT 4096
#define CD 1024
#define CH 16
#define CK 64
#define CF 4096
#define CN (CB*CT)          // 16384 tokens

#define LN_EPS  1e-5f
#define DEN_EPS 1e-6f

// ---------------------------------------------------------------------------
// Scratch (allocation-free: __device__ globals)
// ---------------------------------------------------------------------------
__device__ float g_xn  [(size_t)CN*CD];
__device__ float g_q   [(size_t)CN*CD];
__device__ float g_k   [(size_t)CN*CD];
__device__ float g_v   [(size_t)CN*CD];
__device__ float g_attn[(size_t)CN*CD];
__device__ float g_x2  [(size_t)CN*CD];
__device__ float g_y   [(size_t)CN*CD];
__device__ float g_h   [(size_t)CN*CF];
__device__ float g_kv  [CB*CH*CK*CK];
__device__ float g_ksum[CB*CH*CK];

// ---------------------------------------------------------------------------
// LayerNorm: one block per row (1024 elems), 256 threads x float4
// ---------------------------------------------------------------------------
__device__ __forceinline__ float block_sum_256(float v, float* red) {
    #pragma unroll
    for (int o = 16; o > 0; o >>= 1) v += __shfl_xor_sync(0xffffffffu, v, o);
    if ((threadIdx.x & 31) == 0) red[threadIdx.x >> 5] = v;
    __syncthreads();
    if (threadIdx.x < 32) {
        float t = (threadIdx.x < 8) ? red[threadIdx.x] : 0.f;
        #pragma unroll
        for (int o = 4; o > 0; o >>= 1) t += __shfl_xor_sync(0xffffffffu, t, o);
        if (threadIdx.x == 0) red[8] = t;
    }
    __syncthreads();
    return red[8];
}

__global__ void ln_kernel(const float* __restrict__ x,
                          const float* __restrict__ w,
                          const float* __restrict__ b,
                          float* __restrict__ y)
{
    __shared__ float red[9];
    int row = blockIdx.x;
    int tid = threadIdx.x;
    const float4* xr = reinterpret_cast<const float4*>(x + (size_t)row * CD);
    float4 v = xr[tid];

    float s = v.x + v.y + v.z + v.w;
    float mean = block_sum_256(s, red) * (1.f / CD);

    float dx = v.x - mean, dy = v.y - mean, dz = v.z - mean, dw = v.w - mean;
    float s2 = dx*dx + dy*dy + dz*dz + dw*dw;
    float var = block_sum_256(s2, red) * (1.f / CD);
    float rs = rsqrtf(var + LN_EPS);

    float4 wv = reinterpret_cast<const float4*>(w)[tid];
    float4 bv = reinterpret_cast<const float4*>(b)[tid];
    float4 o;
    o.x = dx * rs * wv.x + bv.x;
    o.y = dy * rs * wv.y + bv.y;
    o.z = dz * rs * wv.z + bv.z;
    o.w = dw * rs * wv.w + bv.w;
    reinterpret_cast<float4*>(y + (size_t)row * CD)[tid] = o;
}

// ---------------------------------------------------------------------------
// tf32 -> b32 conversion (round to nearest)
// ---------------------------------------------------------------------------
__device__ __forceinline__ unsigned f2tf(float x) {
    unsigned r;
    asm("cvt.rna.tf32.f32 %0, %1;" : "=r"(r) : "f"(x));
    return r;
}

// ---------------------------------------------------------------------------
// tf32 tensor-core GEMM: C[N,M] = A[N,Kd] @ W[Kd,M] + bias (+ epilogue)
// 128x128x32 block tile, 256 threads = 8 warps (2 along M x 4 along N),
// warp tile 64x32 = 4x4 m16n8k8 MMA fragments.
// Smem: As2[m][k] stride 36  (frag-read banks (4g+th)%32 -> conflict free,
//                             STS.128 staging conflict free)
//       Bs [k][n] stride 136 (frag-read banks (8th+g)%32 -> conflict free,
//                             STS.128 staging conflict free)
// epi: 0=none, 1=phi(elu+1), 2=gelu(exact erf), 3=+res
// ---------------------------------------------------------------------------
#define GBM 128
#define GBN 128
#define GBK 32
#define ASTR 36
#define BSTR 136

__global__ __launch_bounds__(256, 2) void gemm_tc_kernel(
    const float* __restrict__ A, const float* __restrict__ W,
    const float* __restrict__ bias, const float* __restrict__ res,
    float* __restrict__ C, int M, int Kd, int epi)
{
    __shared__ unsigned As2[GBM][ASTR];   // [m][k]
    __shared__ unsigned Bs [GBK][BSTR];   // [k][n]

    int tid  = threadIdx.x;
    int warp = tid >> 5;
    int lane = tid & 31;
    int g  = lane >> 2;     // 0..7
    int th = lane & 3;      // 0..3
    int wm = (warp & 1) * 64;   // warp M offset in tile
    int wn = (warp >> 1) * 32;  // warp N offset in tile

    int bm = blockIdx.y * GBM;
    int bn = blockIdx.x * GBN;

    const float* Aptr = A + (size_t)bm * Kd;
    const float* Wptr = W + bn;

    float acc[4][4][4];
    #pragma unroll
    for (int i = 0; i < 4; i++)
        #pragma unroll
        for (int j = 0; j < 4; j++)
            #pragma unroll
            for (int c = 0; c < 4; c++) acc[i][j][c] = 0.f;

    for (int k0 = 0; k0 < Kd; k0 += GBK) {
        // ---- Stage A tile: 128 x 32 floats = 1024 float4, 4 per thread ----
        #pragma unroll
        for (int i = 0; i < 4; i++) {
            int f  = tid + i * 256;        // 0..1023
            int r  = f >> 3;               // 0..127
            int cv = (f & 7) << 2;         // 0,4,...,28
            float4 a = *reinterpret_cast<const float4*>(Aptr + (size_t)r * Kd + k0 + cv);
            As2[r][cv + 0] = f2tf(a.x);
            As2[r][cv + 1] = f2tf(a.y);
            As2[r][cv + 2] = f2tf(a.z);
            As2[r][cv + 3] = f2tf(a.w);
        }
        // ---- Stage B tile: 32 x 128 floats = 1024 float4 ----
        #pragma unroll
        for (int i = 0; i < 4; i++) {
            int f = tid + i * 256;
            int r = f >> 5;                // 0..31
            int c = (f & 31) << 2;         // 0..124
            float4 b = *reinterpret_cast<const float4*>(Wptr + (size_t)(k0 + r) * M + c);
            Bs[r][c + 0] = f2tf(b.x);
            Bs[r][c + 1] = f2tf(b.y);
            Bs[r][c + 2] = f2tf(b.z);
            Bs[r][c + 3] = f2tf(b.w);
        }
        __syncthreads();

        #pragma unroll
        for (int ks = 0; ks < GBK; ks += 8) {
            unsigned af[4][4], bf[4][2];
            #pragma unroll
            for (int mt = 0; mt < 4; mt++) {
                int mb = wm + mt * 16;
                af[mt][0] = As2[mb + g    ][ks + th    ];
                af[mt][1] = As2[mb + 8 + g][ks + th    ];
                af[mt][2] = As2[mb + g    ][ks + th + 4];
                af[mt][3] = As2[mb + 8 + g][ks + th + 4];
            }
            #pragma unroll
            for (int nt = 0; nt < 4; nt++) {
                int nb = wn + nt * 8 + g;
                bf[nt][0] = Bs[ks + th    ][nb];
                bf[nt][1] = Bs[ks + th + 4][nb];
            }
            #pragma unroll
            for (int mt = 0; mt < 4; mt++)
                #pragma unroll
                for (int nt = 0; nt < 4; nt++) {
                    asm volatile(
                        "mma.sync.aligned.m16n8k8.row.col.f32.tf32.tf32.f32 "
                        "{%0,%1,%2,%3}, {%4,%5,%6,%7}, {%8,%9}, {%0,%1,%2,%3};"
                        : "+f"(acc[mt][nt][0]), "+f"(acc[mt][nt][1]),
                          "+f"(acc[mt][nt][2]), "+f"(acc[mt][nt][3])
                        : "r"(af[mt][0]), "r"(af[mt][1]), "r"(af[mt][2]), "r"(af[mt][3]),
                          "r"(bf[nt][0]), "r"(bf[nt][1]));
                }
        }
        __syncthreads();
    }

    // ---- Epilogue: each acc fragment -> 2 float2 stores ----
    #pragma unroll
    for (int mt = 0; mt < 4; mt++) {
        #pragma unroll
        for (int nt = 0; nt < 4; nt++) {
            int col = bn + wn + nt * 8 + 2 * th;
            float b0 = bias[col], b1 = bias[col + 1];
            #pragma unroll
            for (int hrow = 0; hrow < 2; hrow++) {
                int row = bm + wm + mt * 16 + g + hrow * 8;
                float v0 = acc[mt][nt][2 * hrow]     + b0;
                float v1 = acc[mt][nt][2 * hrow + 1] + b1;
                if (epi == 1) {
                    v0 = (v0 > 0.f) ? (v0 + 1.f) : expf(v0);
                    v1 = (v1 > 0.f) ? (v1 + 1.f) : expf(v1);
                } else if (epi == 2) {
                    v0 = 0.5f * v0 * (1.f + erff(v0 * 0.7071067811865475f));
                    v1 = 0.5f * v1 * (1.f + erff(v1 * 0.7071067811865475f));
                } else if (epi == 3) {
                    const float2 r2 = *reinterpret_cast<const float2*>(
                        res + (size_t)row * M + col);
                    v0 += r2.x; v1 += r2.y;
                }
                float2 o2 = make_float2(v0, v1);
                *reinterpret_cast<float2*>(C + (size_t)row * M + col) = o2;
            }
        }
    }
}

// ---------------------------------------------------------------------------
// Zero a float buffer
// ---------------------------------------------------------------------------
__global__ void zero_kernel(float* p, int n) {
    int i = blockIdx.x * 256 + threadIdx.x;
    if (i < n) p[i] = 0.f;
}

// ---------------------------------------------------------------------------
// kv[bh][k][v] = sum_s keep_s * phi_k[s][k] * v[s][v]  ;  ksum[bh][k]
// grid (64 bh, 8 chunks), 256 threads, each thread owns a 4x4 kv microtile
// ---------------------------------------------------------------------------
__global__ void kv_kernel(const float* __restrict__ pk,
                          const float* __restrict__ vv,
                          const unsigned char* __restrict__ mask)
{
    __shared__ float sp[8][CK];
    __shared__ float sv[8][CK];

    int bh = blockIdx.x;           // 0..63
    int chunk = blockIdx.y;        // 0..7
    int b = bh / CH, h = bh % CH;
    int t0 = chunk * (CT / 8);     // 512 tokens per chunk

    int tid = threadIdx.x;
    int r0 = (tid >> 4) << 2;      // 0..60
    int c0 = (tid & 15) << 2;      // 0..60

    float acc[4][4];
    #pragma unroll
    for (int i = 0; i < 4; i++)
        #pragma unroll
        for (int j = 0; j < 4; j++) acc[i][j] = 0.f;
    float ks = 0.f;

    for (int g = 0; g < 512; g += 8) {
        #pragma unroll
        for (int i = 0; i < 2; i++) {
            int e = tid + i * 256;          // 0..511
            int s = e >> 6, col = e & 63;
            int t = t0 + g + s;
            size_t rowm = (size_t)b * CT + t;
            float keep = mask[rowm] ? 0.f : 1.f;
            size_t idx = rowm * CD + (size_t)h * CK + col;
            sp[s][col] = pk[idx] * keep;
            sv[s][col] = vv[idx] * keep;
        }
        __syncthreads();
        #pragma unroll
        for (int s = 0; s < 8; s++) {
            float4 a  = *reinterpret_cast<const float4*>(&sp[s][r0]);
            float4 bb = *reinterpret_cast<const float4*>(&sv[s][c0]);
            float ar[4] = {a.x, a.y, a.z, a.w};
            float br[4] = {bb.x, bb.y, bb.z, bb.w};
            #pragma unroll
            for (int i = 0; i < 4; i++)
                #pragma unroll
                for (int j = 0; j < 4; j++)
                    acc[i][j] += ar[i] * br[j];
        }
        if (tid < CK) {
            #pragma unroll
            for (int s = 0; s < 8; s++) ks += sp[s][tid];
        }
        __syncthreads();
    }

    float* kvp = g_kv + (size_t)bh * CK * CK;
    #pragma unroll
    for (int i = 0; i < 4; i++)
        #pragma unroll
        for (int j = 0; j < 4; j++)
            atomicAdd(&kvp[(r0 + i) * CK + c0 + j], acc[i][j]);
    if (tid < CK) atomicAdd(&g_ksum[bh * CK + tid], ks);
}

// ---------------------------------------------------------------------------
// attn[t][c] = (phi_q[t] . kv[:,c]) / (phi_q[t] . ksum + eps)
// grid (64 bh, 32 token-blocks of 128), 256 threads = 8 warps x 16 tokens
// ---------------------------------------------------------------------------
__global__ void attn_kernel(const float* __restrict__ pq,
                            float* __restrict__ attn)
{
    __shared__ float skv[CK][CK];
    __shared__ float sks[CK];
    __shared__ float sq[8][CK];

    int bh = blockIdx.x, tb = blockIdx.y;
    int b = bh / CH, h = bh % CH;
    int tid = threadIdx.x;

    const float* kvp = g_kv + (size_t)bh * CK * CK;
    for (int i = tid; i < CK * CK; i += 256) skv[i >> 6][i & 63] = kvp[i];
    if (tid < CK) sks[tid] = g_ksum[bh * CK + tid];
    __syncthreads();

    int w = tid >> 5, l = tid & 31;
    for (int it = 0; it < 16; it++) {
        int t = tb * 128 + w * 16 + it;
        size_t rowp = ((size_t)b * CT + t) * CD + (size_t)h * CK;
        sq[w][l]      = pq[rowp + l];
        sq[w][l + 32] = pq[rowp + l + 32];
        __syncwarp();
        float n0 = 0.f, n1 = 0.f, den = DEN_EPS;
        #pragma unroll
        for (int k = 0; k < CK; k++) {
            float qv = sq[w][k];
            n0  += qv * skv[k][l];
            n1  += qv * skv[k][l + 32];
            den += qv * sks[k];
        }
        float inv = 1.f / den;
        attn[rowp + l]      = n0 * inv;
        attn[rowp + l + 32] = n1 * inv;
        __syncwarp();
    }
}

// ---------------------------------------------------------------------------
// Host launcher
// ---------------------------------------------------------------------------
extern "C" void kernel_launch(void* const* d_in, const int* in_sizes, int n_in,
                              void* d_out, int out_size)
{
    const float* x    = (const float*)d_in[0];
    const unsigned char* mask = (const unsigned char*)d_in[1];
    const float* Wq   = (const float*)d_in[2];
    const float* bq   = (const float*)d_in[3];
    const float* Wk   = (const float*)d_in[4];
    const float* bk   = (const float*)d_in[5];
    const float* Wv   = (const float*)d_in[6];
    const float* bv   = (const float*)d_in[7];
    const float* Wo   = (const float*)d_in[8];
    const float* bo   = (const float*)d_in[9];
    const float* ln1w = (const float*)d_in[10];
    const float* ln1b = (const float*)d_in[11];
    const float* ln2w = (const float*)d_in[12];
    const float* ln2b = (const float*)d_in[13];
    const float* W1   = (const float*)d_in[14];
    const float* b1   = (const float*)d_in[15];
    const float* W2   = (const float*)d_in[16];
    const float* b2   = (const float*)d_in[17];
    float* out = (float*)d_out;

    void *pxn, *pq, *pk, *pv, *pattn, *px2, *py, *ph, *pkv, *pks;
    cudaGetSymbolAddress(&pxn, g_xn);
    cudaGetSymbolAddress(&pq, g_q);
    cudaGetSymbolAddress(&pk, g_k);
    cudaGetSymbolAddress(&pv, g_v);
    cudaGetSymbolAddress(&pattn, g_attn);
    cudaGetSymbolAddress(&px2, g_x2);
    cudaGetSymbolAddress(&py, g_y);
    cudaGetSymbolAddress(&ph, g_h);
    cudaGetSymbolAddress(&pkv, g_kv);
    cudaGetSymbolAddress(&pks, g_ksum);

    float* xn   = (float*)pxn;
    float* qb   = (float*)pq;
    float* kb   = (float*)pk;
    float* vb   = (float*)pv;
    float* atb  = (float*)pattn;
    float* x2   = (float*)px2;
    float* yb   = (float*)py;
    float* hb   = (float*)ph;
    float* kvb  = (float*)pkv;
    float* ksb  = (float*)pks;

    // 1. LN1
    ln_kernel<<<CN, 256>>>(x, ln1w, ln1b, xn);

    // 2-4. QKV projections (phi fused into Q,K)
    dim3 gD(CD / GBN, CN / GBM);
    gemm_tc_kernel<<<gD, 256>>>(xn, Wq, bq, nullptr, qb, CD, CD, 1);
    gemm_tc_kernel<<<gD, 256>>>(xn, Wk, bk, nullptr, kb, CD, CD, 1);
    gemm_tc_kernel<<<gD, 256>>>(xn, Wv, bv, nullptr, vb, CD, CD, 0);

    // 5. zero kv/ksum accumulators
    zero_kernel<<<(CB*CH*CK*CK + 255) / 256, 256>>>(kvb, CB*CH*CK*CK);
    zero_kernel<<<(CB*CH*CK + 255) / 256, 256>>>(ksb, CB*CH*CK);

    // 6. kv + ksum reduction (masked)
    kv_kernel<<<dim3(CB*CH, 8), 256>>>(kb, vb, mask);

    // 7. numerator / denominator
    attn_kernel<<<dim3(CB*CH, CT / 128), 256>>>(qb, atb);

    // 8. O projection + residual
    gemm_tc_kernel<<<gD, 256>>>(atb, Wo, bo, x, x2, CD, CD, 3);

    // 9. LN2
    ln_kernel<<<CN, 256>>>(x2, ln2w, ln2b, yb);

    // 10. FFN1 + exact GELU
    dim3 gF(CF / GBN, CN / GBM);
    gemm_tc_kernel<<<gF, 256>>>(yb, W1, b1, nullptr, hb, CF, CD, 2);

    // 11. FFN2 + residual -> output
    gemm_tc_kernel<<<gD, 256>>>(hb, W2, b2, x2, out, CD, CF, 3);
}

// round 4
// speedup vs baseline: 3.8189x; 1.3205x over previous
#include <cuda_runtime.h>
#include <cuda_bf16.h>
#include <math.h>
#include <stdint.h>

// Problem constants
#define CB 4
#define CT 4096
#define CD 1024
#define CH 16
#define CK 64
#define CF 4096
#define CN (CB*CT)          // 16384 tokens

#define LN_EPS  1e-5f
#define DEN_EPS 1e-6f

// ---------------------------------------------------------------------------
// Scratch (allocation-free: __device__ globals)
// ---------------------------------------------------------------------------
__device__ float g_xn  [(size_t)CN*CD];
__device__ float g_q   [(size_t)CN*CD];
__device__ float g_k   [(size_t)CN*CD];
__device__ float g_v   [(size_t)CN*CD];
__device__ float g_attn[(size_t)CN*CD];
__device__ float g_x2  [(size_t)CN*CD];
__device__ float g_y   [(size_t)CN*CD];
__device__ float g_h   [(size_t)CN*CF];
__device__ float g_kv  [CB*CH*CK*CK];
__device__ float g_ksum[CB*CH*CK];
__device__ float g_wt  [12u*1024u*1024u];   // tf32-rounded weights (same layout)

// Offsets into g_wt (floats)
#define WT_Q 0u
#define WT_K (1u*1024u*1024u)
#define WT_V (2u*1024u*1024u)
#define WT_O (3u*1024u*1024u)
#define WT_1 (4u*1024u*1024u)
#define WT_2 (8u*1024u*1024u)

// ---------------------------------------------------------------------------
// Helpers
// ---------------------------------------------------------------------------
__device__ __forceinline__ unsigned f2tf(float x) {
    unsigned r; asm("cvt.rna.tf32.f32 %0, %1;" : "=r"(r) : "f"(x)); return r;
}
__device__ __forceinline__ float tfr(float x) { return __uint_as_float(f2tf(x)); }

__device__ __forceinline__ uint32_t s2u(const void* p) {
    uint32_t a;
    asm("{ .reg .u64 t; cvta.to.shared.u64 t, %1; cvt.u32.u64 %0, t; }" : "=r"(a) : "l"(p));
    return a;
}
__device__ __forceinline__ void cpa16(uint32_t d, const void* s) {
    asm volatile("cp.async.cg.shared.global [%0], [%1], 16;" :: "r"(d), "l"(s));
}
#define CP_COMMIT() asm volatile("cp.async.commit_group;" ::: "memory")
#define CP_WAIT0()  asm volatile("cp.async.wait_group 0;" ::: "memory")

// ---------------------------------------------------------------------------
// LayerNorm: one block per row (1024 elems), 256 threads x float4
// Output rounded to tf32 grid (feeds tensor-core GEMMs)
// ---------------------------------------------------------------------------
__device__ __forceinline__ float block_sum_256(float v, float* red) {
    #pragma unroll
    for (int o = 16; o > 0; o >>= 1) v += __shfl_xor_sync(0xffffffffu, v, o);
    if ((threadIdx.x & 31) == 0) red[threadIdx.x >> 5] = v;
    __syncthreads();
    if (threadIdx.x < 32) {
        float t = (threadIdx.x < 8) ? red[threadIdx.x] : 0.f;
        #pragma unroll
        for (int o = 4; o > 0; o >>= 1) t += __shfl_xor_sync(0xffffffffu, t, o);
        if (threadIdx.x == 0) red[8] = t;
    }
    __syncthreads();
    return red[8];
}

__global__ void ln_kernel(const float* __restrict__ x,
                          const float* __restrict__ w,
                          const float* __restrict__ b,
                          float* __restrict__ y)
{
    __shared__ float red[9];
    int row = blockIdx.x;
    int tid = threadIdx.x;
    const float4* xr = reinterpret_cast<const float4*>(x + (size_t)row * CD);
    float4 v = xr[tid];

    float s = v.x + v.y + v.z + v.w;
    float mean = block_sum_256(s, red) * (1.f / CD);

    float dx = v.x - mean, dy = v.y - mean, dz = v.z - mean, dw = v.w - mean;
    float s2 = dx*dx + dy*dy + dz*dz + dw*dw;
    float var = block_sum_256(s2, red) * (1.f / CD);
    float rs = rsqrtf(var + LN_EPS);

    float4 wv = reinterpret_cast<const float4*>(w)[tid];
    float4 bv = reinterpret_cast<const float4*>(b)[tid];
    float4 o;
    o.x = tfr(dx * rs * wv.x + bv.x);
    o.y = tfr(dy * rs * wv.y + bv.y);
    o.z = tfr(dz * rs * wv.z + bv.z);
    o.w = tfr(dw * rs * wv.w + bv.w);
    reinterpret_cast<float4*>(y + (size_t)row * CD)[tid] = o;
}

// ---------------------------------------------------------------------------
// Round a weight buffer to the tf32 grid (one-time per launch)
// ---------------------------------------------------------------------------
__global__ void wround_kernel(const float* __restrict__ src,
                              float* __restrict__ dst, int n)
{
    int i = blockIdx.x * 256 + threadIdx.x;
    if (i < n) {
        float4 v = reinterpret_cast<const float4*>(src)[i];
        v.x = tfr(v.x); v.y = tfr(v.y); v.z = tfr(v.z); v.w = tfr(v.w);
        reinterpret_cast<float4*>(dst)[i] = v;
    }
}

// ---------------------------------------------------------------------------
// tf32 tensor-core GEMM with cp.async double buffering.
// C[N,M] = A[N,Kd] @ W[Kd,M] + bias (+ epilogue)
// 128x128x32 block tile, 256 threads = 8 warps (2 along M x 4 along N),
// warp tile 64x32 = 4x4 m16n8k8 fragments. A,W pre-rounded to tf32 grid.
// Smem rows padded: A 32+4 floats (144B), B 128+8 floats (544B) -> both
// cp.async-16B-aligned and conflict-free for fragment reads.
// epi: 0=none, 1=phi(elu+1), 2=gelu->tf32, 3=+res
// ---------------------------------------------------------------------------
#define GBM 128
#define GBN 128
#define GBK 32
#define ASTR 36                 // floats per A smem row
#define BSTR 136                // floats per B smem row
#define STG_A_FLOATS (GBM*ASTR) // 4608
#define STG_B_FLOATS (GBK*BSTR) // 4352
#define STG_FLOATS   (STG_A_FLOATS + STG_B_FLOATS)   // 8960
#define GEMM_SMEM    (2*STG_FLOATS*4)                // 71680 bytes

__global__ __launch_bounds__(256, 2) void gemm_tc_kernel(
    const float* __restrict__ A, const float* __restrict__ W,
    const float* __restrict__ bias, const float* __restrict__ res,
    float* __restrict__ C, int M, int Kd, int epi)
{
    extern __shared__ float smem[];
    uint32_t sbase = s2u(smem);

    int tid  = threadIdx.x;
    int warp = tid >> 5;
    int lane = tid & 31;
    int g  = lane >> 2;         // 0..7
    int th = lane & 3;          // 0..3
    int wm = (warp & 1) * 64;
    int wn = (warp >> 1) * 32;

    int bm = blockIdx.y * GBM;
    int bn = blockIdx.x * GBN;

    const float* Aptr = A + (size_t)bm * Kd;
    const float* Wptr = W + bn;

    // staging thread roles (fixed)
    int ar = tid >> 1;                 // A row pair handled below
    int ac = (tid & 1) << 2;           // (unused pattern replaced)

    float acc[4][4][4];
    #pragma unroll
    for (int i = 0; i < 4; i++)
        #pragma unroll
        for (int j = 0; j < 4; j++)
            #pragma unroll
            for (int c = 0; c < 4; c++) acc[i][j][c] = 0.f;

    int NB = Kd >> 5;

    // ---- fill stage 0 ----
    {
        uint32_t sA = sbase;
        uint32_t sB = sbase + STG_A_FLOATS * 4;
        #pragma unroll
        for (int j = 0; j < 4; j++) {
            int e = tid + j * 256;          // 0..1023
            int r = e >> 3, c = e & 7;      // A: 128 rows x 8 chunks
            cpa16(sA + (r * ASTR + c * 4) * 4, Aptr + (size_t)r * Kd + c * 4);
        }
        #pragma unroll
        for (int j = 0; j < 4; j++) {
            int e = tid + j * 256;
            int r = e >> 5, c = e & 31;     // B: 32 rows x 32 chunks
            cpa16(sB + (r * BSTR + c * 4) * 4, Wptr + (size_t)r * M + c * 4);
        }
        CP_COMMIT();
    }

    for (int i = 0; i < NB; i++) {
        int s = i & 1;
        CP_WAIT0();
        __syncthreads();

        // issue next-stage loads (overlap with this stage's MMAs)
        if (i + 1 < NB) {
            int s2 = s ^ 1;
            int k0 = (i + 1) * GBK;
            uint32_t sA = sbase + (uint32_t)s2 * STG_FLOATS * 4;
            uint32_t sB = sA + STG_A_FLOATS * 4;
            const float* ap = Aptr + k0;
            const float* wp = Wptr + (size_t)k0 * M;
            #pragma unroll
            for (int j = 0; j < 4; j++) {
                int e = tid + j * 256;
                int r = e >> 3, c = e & 7;
                cpa16(sA + (r * ASTR + c * 4) * 4, ap + (size_t)r * Kd + c * 4);
            }
            #pragma unroll
            for (int j = 0; j < 4; j++) {
                int e = tid + j * 256;
                int r = e >> 5, c = e & 31;
                cpa16(sB + (r * BSTR + c * 4) * 4, wp + (size_t)r * M + c * 4);
            }
            CP_COMMIT();
        }

        const float* As = smem + (size_t)s * STG_FLOATS;
        const float* Bs = As + STG_A_FLOATS;

        #pragma unroll
        for (int ks = 0; ks < GBK; ks += 8) {
            unsigned af[4][4], bf[4][2];
            #pragma unroll
            for (int mt = 0; mt < 4; mt++) {
                int mb = wm + mt * 16;
                af[mt][0] = __float_as_uint(As[(mb + g    ) * ASTR + ks + th    ]);
                af[mt][1] = __float_as_uint(As[(mb + 8 + g) * ASTR + ks + th    ]);
                af[mt][2] = __float_as_uint(As[(mb + g    ) * ASTR + ks + th + 4]);
                af[mt][3] = __float_as_uint(As[(mb + 8 + g) * ASTR + ks + th + 4]);
            }
            #pragma unroll
            for (int nt = 0; nt < 4; nt++) {
                int nb = wn + nt * 8 + g;
                bf[nt][0] = __float_as_uint(Bs[(ks + th    ) * BSTR + nb]);
                bf[nt][1] = __float_as_uint(Bs[(ks + th + 4) * BSTR + nb]);
            }
            #pragma unroll
            for (int mt = 0; mt < 4; mt++)
                #pragma unroll
                for (int nt = 0; nt < 4; nt++) {
                    asm volatile(
                        "mma.sync.aligned.m16n8k8.row.col.f32.tf32.tf32.f32 "
                        "{%0,%1,%2,%3}, {%4,%5,%6,%7}, {%8,%9}, {%0,%1,%2,%3};"
                        : "+f"(acc[mt][nt][0]), "+f"(acc[mt][nt][1]),
                          "+f"(acc[mt][nt][2]), "+f"(acc[mt][nt][3])
                        : "r"(af[mt][0]), "r"(af[mt][1]), "r"(af[mt][2]), "r"(af[mt][3]),
                          "r"(bf[nt][0]), "r"(bf[nt][1]));
                }
        }
    }

    // ---- Epilogue ----
    #pragma unroll
    for (int mt = 0; mt < 4; mt++) {
        #pragma unroll
        for (int nt = 0; nt < 4; nt++) {
            int col = bn + wn + nt * 8 + 2 * th;
            float b0 = bias[col], b1 = bias[col + 1];
            #pragma unroll
            for (int hrow = 0; hrow < 2; hrow++) {
                int row = bm + wm + mt * 16 + g + hrow * 8;
                float v0 = acc[mt][nt][2 * hrow]     + b0;
                float v1 = acc[mt][nt][2 * hrow + 1] + b1;
                if (epi == 1) {
                    v0 = (v0 > 0.f) ? (v0 + 1.f) : expf(v0);
                    v1 = (v1 > 0.f) ? (v1 + 1.f) : expf(v1);
                } else if (epi == 2) {
                    v0 = tfr(0.5f * v0 * (1.f + erff(v0 * 0.7071067811865475f)));
                    v1 = tfr(0.5f * v1 * (1.f + erff(v1 * 0.7071067811865475f)));
                } else if (epi == 3) {
                    const float2 r2 = *reinterpret_cast<const float2*>(
                        res + (size_t)row * M + col);
                    v0 += r2.x; v1 += r2.y;
                }
                float2 o2 = make_float2(v0, v1);
                *reinterpret_cast<float2*>(C + (size_t)row * M + col) = o2;
            }
        }
    }
}

// ---------------------------------------------------------------------------
// Zero a float buffer
// ---------------------------------------------------------------------------
__global__ void zero_kernel(float* p, int n) {
    int i = blockIdx.x * 256 + threadIdx.x;
    if (i < n) p[i] = 0.f;
}

// ---------------------------------------------------------------------------
// kv[bh][k][v] = sum_s keep_s * phi_k[s][k] * v[s][v]  ;  ksum[bh][k]
// ---------------------------------------------------------------------------
__global__ void kv_kernel(const float* __restrict__ pk,
                          const float* __restrict__ vv,
                          const unsigned char* __restrict__ mask)
{
    __shared__ float sp[8][CK];
    __shared__ float sv[8][CK];

    int bh = blockIdx.x;
    int chunk = blockIdx.y;
    int b = bh / CH, h = bh % CH;
    int t0 = chunk * (CT / 8);

    int tid = threadIdx.x;
    int r0 = (tid >> 4) << 2;
    int c0 = (tid & 15) << 2;

    float acc[4][4];
    #pragma unroll
    for (int i = 0; i < 4; i++)
        #pragma unroll
        for (int j = 0; j < 4; j++) acc[i][j] = 0.f;
    float ks = 0.f;

    for (int g = 0; g < 512; g += 8) {
        #pragma unroll
        for (int i = 0; i < 2; i++) {
            int e = tid + i * 256;
            int s = e >> 6, col = e & 63;
            int t = t0 + g + s;
            size_t rowm = (size_t)b * CT + t;
            float keep = mask[rowm] ? 0.f : 1.f;
            size_t idx = rowm * CD + (size_t)h * CK + col;
            sp[s][col] = pk[idx] * keep;
            sv[s][col] = vv[idx] * keep;
        }
        __syncthreads();
        #pragma unroll
        for (int s = 0; s < 8; s++) {
            float4 a  = *reinterpret_cast<const float4*>(&sp[s][r0]);
            float4 bb = *reinterpret_cast<const float4*>(&sv[s][c0]);
            float ar[4] = {a.x, a.y, a.z, a.w};
            float br[4] = {bb.x, bb.y, bb.z, bb.w};
            #pragma unroll
            for (int i = 0; i < 4; i++)
                #pragma unroll
                for (int j = 0; j < 4; j++)
                    acc[i][j] += ar[i] * br[j];
        }
        if (tid < CK) {
            #pragma unroll
            for (int s = 0; s < 8; s++) ks += sp[s][tid];
        }
        __syncthreads();
    }

    float* kvp = g_kv + (size_t)bh * CK * CK;
    #pragma unroll
    for (int i = 0; i < 4; i++)
        #pragma unroll
        for (int j = 0; j < 4; j++)
            atomicAdd(&kvp[(r0 + i) * CK + c0 + j], acc[i][j]);
    if (tid < CK) atomicAdd(&g_ksum[bh * CK + tid], ks);
}

// ---------------------------------------------------------------------------
// attn[t][c] = (phi_q[t] . kv[:,c]) / (phi_q[t] . ksum + eps)   (tf32-rounded)
// ---------------------------------------------------------------------------
__global__ void attn_kernel(const float* __restrict__ pq,
                            float* __restrict__ attn)
{
    __shared__ float skv[CK][CK];
    __shared__ float sks[CK];
    __shared__ float sq[8][CK];

    int bh = blockIdx.x, tb = blockIdx.y;
    int b = bh / CH, h = bh % CH;
    int tid = threadIdx.x;

    const float* kvp = g_kv + (size_t)bh * CK * CK;
    for (int i = tid; i < CK * CK; i += 256) skv[i >> 6][i & 63] = kvp[i];
    if (tid < CK) sks[tid] = g_ksum[bh * CK + tid];
    __syncthreads();

    int w = tid >> 5, l = tid & 31;
    for (int it = 0; it < 16; it++) {
        int t = tb * 128 + w * 16 + it;
        size_t rowp = ((size_t)b * CT + t) * CD + (size_t)h * CK;
        sq[w][l]      = pq[rowp + l];
        sq[w][l + 32] = pq[rowp + l + 32];
        __syncwarp();
        float n0 = 0.f, n1 = 0.f, den = DEN_EPS;
        #pragma unroll
        for (int k = 0; k < CK; k++) {
            float qv = sq[w][k];
            n0  += qv * skv[k][l];
            n1  += qv * skv[k][l + 32];
            den += qv * sks[k];
        }
        float inv = 1.f / den;
        attn[rowp + l]      = tfr(n0 * inv);
        attn[rowp + l + 32] = tfr(n1 * inv);
        __syncwarp();
    }
}

// ---------------------------------------------------------------------------
// Host launcher
// ---------------------------------------------------------------------------
extern "C" void kernel_launch(void* const* d_in, const int* in_sizes, int n_in,
                              void* d_out, int out_size)
{
    const float* x    = (const float*)d_in[0];
    const unsigned char* mask = (const unsigned char*)d_in[1];
    const float* Wq   = (const float*)d_in[2];
    const float* bq   = (const float*)d_in[3];
    const float* Wk   = (const float*)d_in[4];
    const float* bk   = (const float*)d_in[5];
    const float* Wv   = (const float*)d_in[6];
    const float* bv   = (const float*)d_in[7];
    const float* Wo   = (const float*)d_in[8];
    const float* bo   = (const float*)d_in[9];
    const float* ln1w = (const float*)d_in[10];
    const float* ln1b = (const float*)d_in[11];
    const float* ln2w = (const float*)d_in[12];
    const float* ln2b = (const float*)d_in[13];
    const float* W1   = (const float*)d_in[14];
    const float* b1   = (const float*)d_in[15];
    const float* W2   = (const float*)d_in[16];
    const float* b2   = (const float*)d_in[17];
    float* out = (float*)d_out;

    void *pxn, *pq, *pk, *pv, *pattn, *px2, *py, *ph, *pkv, *pks, *pwt;
    cudaGetSymbolAddress(&pxn, g_xn);
    cudaGetSymbolAddress(&pq, g_q);
    cudaGetSymbolAddress(&pk, g_k);
    cudaGetSymbolAddress(&pv, g_v);
    cudaGetSymbolAddress(&pattn, g_attn);
    cudaGetSymbolAddress(&px2, g_x2);
    cudaGetSymbolAddress(&py, g_y);
    cudaGetSymbolAddress(&ph, g_h);
    cudaGetSymbolAddress(&pkv, g_kv);
    cudaGetSymbolAddress(&pks, g_ksum);
    cudaGetSymbolAddress(&pwt, g_wt);

    float* xn   = (float*)pxn;
    float* qb   = (float*)pq;
    float* kb   = (float*)pk;
    float* vb   = (float*)pv;
    float* atb  = (float*)pattn;
    float* x2   = (float*)px2;
    float* yb   = (float*)py;
    float* hb   = (float*)ph;
    float* kvb  = (float*)pkv;
    float* ksb  = (float*)pks;
    float* wt   = (float*)pwt;

    cudaFuncSetAttribute(gemm_tc_kernel, cudaFuncAttributeMaxDynamicSharedMemorySize, GEMM_SMEM);

    // 0. Pre-round weights to tf32 grid (keeps cvt out of GEMM hot loop)
    wround_kernel<<<(1024*1024/4 + 255)/256, 256>>>(Wq, wt + WT_Q, 1024*1024/4);
    wround_kernel<<<(1024*1024/4 + 255)/256, 256>>>(Wk, wt + WT_K, 1024*1024/4);
    wround_kernel<<<(1024*1024/4 + 255)/256, 256>>>(Wv, wt + WT_V, 1024*1024/4);
    wround_kernel<<<(1024*1024/4 + 255)/256, 256>>>(Wo, wt + WT_O, 1024*1024/4);
    wround_kernel<<<(4*1024*1024/4 + 255)/256, 256>>>(W1, wt + WT_1, 4*1024*1024/4);
    wround_kernel<<<(4*1024*1024/4 + 255)/256, 256>>>(W2, wt + WT_2, 4*1024*1024/4);

    // 1. LN1 (tf32-rounded output)
    ln_kernel<<<CN, 256>>>(x, ln1w, ln1b, xn);

    // 2-4. QKV projections (phi fused into Q,K)
    dim3 gD(CD / GBN, CN / GBM);
    gemm_tc_kernel<<<gD, 256, GEMM_SMEM>>>(xn, wt + WT_Q, bq, nullptr, qb, CD, CD, 1);
    gemm_tc_kernel<<<gD, 256, GEMM_SMEM>>>(xn, wt + WT_K, bk, nullptr, kb, CD, CD, 1);
    gemm_tc_kernel<<<gD, 256, GEMM_SMEM>>>(xn, wt + WT_V, bv, nullptr, vb, CD, CD, 0);

    // 5. zero kv/ksum accumulators
    zero_kernel<<<(CB*CH*CK*CK + 255) / 256, 256>>>(kvb, CB*CH*CK*CK);
    zero_kernel<<<(CB*CH*CK + 255) / 256, 256>>>(ksb, CB*CH*CK);

    // 6. kv + ksum reduction (masked)
    kv_kernel<<<dim3(CB*CH, 8), 256>>>(kb, vb, mask);

    // 7. numerator / denominator (tf32-rounded output)
    attn_kernel<<<dim3(CB*CH, CT / 128), 256>>>(qb, atb);

    // 8. O projection + residual
    gemm_tc_kernel<<<gD, 256, GEMM_SMEM>>>(atb, wt + WT_O, bo, x, x2, CD, CD, 3);

    // 9. LN2 (tf32-rounded output)
    ln_kernel<<<CN, 256>>>(x2, ln2w, ln2b, yb);

    // 10. FFN1 + exact GELU (tf32-rounded output)
    dim3 gF(CF / GBN, CN / GBM);
    gemm_tc_kernel<<<gF, 256, GEMM_SMEM>>>(yb, wt + WT_1, b1, nullptr, hb, CF, CD, 2);

    // 11. FFN2 + residual -> output
    gemm_tc_kernel<<<gD, 256, GEMM_SMEM>>>(hb, wt + WT_2, b2, x2, out, CD, CF, 3);
}

// round 5
// speedup vs baseline: 5.5099x; 1.4428x over previous
#include <cuda_runtime.h>
#include <cuda_fp16.h>
#include <math.h>
#include <stdint.h>

// Problem constants
#define CB 4
#define CT 4096
#define CD 1024
#define CH 16
#define CK 64
#define CF 4096
#define CN (CB*CT)          // 16384 tokens

#define LN_EPS  1e-5f
#define DEN_EPS 1e-6f

// ---------------------------------------------------------------------------
// Scratch (allocation-free: __device__ globals)
// ---------------------------------------------------------------------------
__device__ __half gh_xn  [(size_t)CN*CD];
__device__ __half gh_q   [(size_t)CN*CD];
__device__ __half gh_k   [(size_t)CN*CD];
__device__ __half gh_v   [(size_t)CN*CD];
__device__ __half gh_attn[(size_t)CN*CD];
__device__ __half gh_y   [(size_t)CN*CD];
__device__ __half gh_h   [(size_t)CN*CF];
__device__ __half gh_w   [12u*1024u*1024u];   // fp16 weights
__device__ float  g_x2   [(size_t)CN*CD];
__device__ float  g_kv   [CB*CH*CK*CK];
__device__ float  g_ksum [CB*CH*CK];

// Offsets into gh_w (halves)
#define WT_Q 0u
#define WT_K (1u*1024u*1024u)
#define WT_V (2u*1024u*1024u)
#define WT_O (3u*1024u*1024u)
#define WT_1 (4u*1024u*1024u)
#define WT_2 (8u*1024u*1024u)

// ---------------------------------------------------------------------------
// Helpers
// ---------------------------------------------------------------------------
__device__ __forceinline__ uint32_t s2u(const void* p) {
    uint32_t a;
    asm("{ .reg .u64 t; cvta.to.shared.u64 t, %1; cvt.u32.u64 %0, t; }" : "=r"(a) : "l"(p));
    return a;
}
__device__ __forceinline__ void cpa16(uint32_t d, const void* s) {
    asm volatile("cp.async.cg.shared.global [%0], [%1], 16;" :: "r"(d), "l"(s));
}
#define CP_COMMIT() asm volatile("cp.async.commit_group;" ::: "memory")
#define CP_WAIT1()  asm volatile("cp.async.wait_group 1;" ::: "memory")

// ---------------------------------------------------------------------------
// LayerNorm: one block per row (1024 elems), 256 threads x float4 -> fp16 out
// ---------------------------------------------------------------------------
__device__ __forceinline__ float block_sum_256(float v, float* red) {
    #pragma unroll
    for (int o = 16; o > 0; o >>= 1) v += __shfl_xor_sync(0xffffffffu, v, o);
    if ((threadIdx.x & 31) == 0) red[threadIdx.x >> 5] = v;
    __syncthreads();
    if (threadIdx.x < 32) {
        float t = (threadIdx.x < 8) ? red[threadIdx.x] : 0.f;
        #pragma unroll
        for (int o = 4; o > 0; o >>= 1) t += __shfl_xor_sync(0xffffffffu, t, o);
        if (threadIdx.x == 0) red[8] = t;
    }
    __syncthreads();
    return red[8];
}

__global__ void ln_kernel(const float* __restrict__ x,
                          const float* __restrict__ w,
                          const float* __restrict__ b,
                          __half* __restrict__ y)
{
    __shared__ float red[9];
    int row = blockIdx.x;
    int tid = threadIdx.x;
    const float4* xr = reinterpret_cast<const float4*>(x + (size_t)row * CD);
    float4 v = xr[tid];

    float s = v.x + v.y + v.z + v.w;
    float mean = block_sum_256(s, red) * (1.f / CD);

    float dx = v.x - mean, dy = v.y - mean, dz = v.z - mean, dw = v.w - mean;
    float s2 = dx*dx + dy*dy + dz*dz + dw*dw;
    float var = block_sum_256(s2, red) * (1.f / CD);
    float rs = rsqrtf(var + LN_EPS);

    float4 wv = reinterpret_cast<const float4*>(w)[tid];
    float4 bv = reinterpret_cast<const float4*>(b)[tid];
    __half2 h0 = __floats2half2_rn(dx * rs * wv.x + bv.x, dy * rs * wv.y + bv.y);
    __half2 h1 = __floats2half2_rn(dz * rs * wv.z + bv.z, dw * rs * wv.w + bv.w);
    __half2* yp = reinterpret_cast<__half2*>(y + (size_t)row * CD + tid * 4);
    yp[0] = h0; yp[1] = h1;
}

// ---------------------------------------------------------------------------
// Weight convert float -> fp16
// ---------------------------------------------------------------------------
__global__ void wconv_kernel(const float* __restrict__ src,
                             __half* __restrict__ dst, int n4)
{
    int i = blockIdx.x * 256 + threadIdx.x;
    if (i < n4) {
        float4 v = reinterpret_cast<const float4*>(src)[i];
        __half2* d = reinterpret_cast<__half2*>(dst + (size_t)i * 4);
        d[0] = __floats2half2_rn(v.x, v.y);
        d[1] = __floats2half2_rn(v.z, v.w);
    }
}

// ---------------------------------------------------------------------------
// fp16 tensor-core GEMM, 3-stage cp.async pipeline, ldmatrix fragments.
// C[N,M] = A[N,Kd] @ W[Kd,M] + bias (+ epilogue), fp32 accumulate.
// 128x128x32 tile, 256 threads = 8 warps (2M x 4N), warp tile 64x32,
// 4x4 m16n8k16 fragments per warp per 16-wide k-step (2 steps per block).
// Smem rows: A padded to 80B (40 halves), B to 272B (136 halves) ->
// ldmatrix + cp.async staging conflict-free.
// epi: 0=none->h, 1=phi(elu+1)->h, 2=gelu->h, 3=+res(f32)->f32
// ---------------------------------------------------------------------------
#define GBM 128
#define GBN 128
#define GBK 32
#define ASTRH 40
#define BSTRH 136
#define STG_A_H (GBM*ASTRH)        // 5120 halves
#define STG_B_H (GBK*BSTRH)        // 4352 halves
#define STG_H   (STG_A_H+STG_B_H)  // 9472 halves
#define NSTG 3
#define GEMM_SMEM (NSTG*STG_H*2)   // 56832 bytes

__device__ __forceinline__ void fill_stage_h(uint32_t sbase, int s,
    const __half* __restrict__ Ab, const __half* __restrict__ Wb,
    int M, int Kd, int k0, int tid)
{
    uint32_t sA = sbase + (uint32_t)s * STG_H * 2;
    uint32_t sB = sA + STG_A_H * 2;
    const __half* ap = Ab + k0;
    const __half* wp = Wb + (size_t)k0 * M;
    #pragma unroll
    for (int j = 0; j < 2; j++) {
        int e = tid + j * 256;          // 0..511
        int r = e >> 2, c = e & 3;      // A: 128 rows x 4 16B-chunks
        cpa16(sA + r * 80 + c * 16, ap + (size_t)r * Kd + c * 8);
    }
    #pragma unroll
    for (int j = 0; j < 2; j++) {
        int e = tid + j * 256;
        int r = e >> 4, c = e & 15;     // B: 32 rows x 16 16B-chunks
        cpa16(sB + r * 272 + c * 16, wp + (size_t)r * M + c * 8);
    }
}

__global__ __launch_bounds__(256, 2) void gemm_h_kernel(
    const __half* __restrict__ A, const __half* __restrict__ W,
    const float* __restrict__ bias, const float* __restrict__ res,
    void* __restrict__ Cout, int M, int Kd, int epi)
{
    extern __shared__ __half smem[];
    uint32_t sbase = s2u(smem);

    int tid  = threadIdx.x;
    int warp = tid >> 5;
    int lane = tid & 31;
    int g  = lane >> 2;
    int th = lane & 3;
    int wm = (warp & 1) * 64;
    int wn = (warp >> 1) * 32;

    int bm = blockIdx.y * GBM;
    int bn = blockIdx.x * GBN;

    const __half* Aptr = A + (size_t)bm * Kd;
    const __half* Wptr = W + bn;

    float acc[4][4][4];
    #pragma unroll
    for (int i = 0; i < 4; i++)
        #pragma unroll
        for (int j = 0; j < 4; j++)
            #pragma unroll
            for (int c = 0; c < 4; c++) acc[i][j][c] = 0.f;

    int NB = Kd >> 5;

    fill_stage_h(sbase, 0, Aptr, Wptr, M, Kd, 0, tid);
    CP_COMMIT();
    fill_stage_h(sbase, 1, Aptr, Wptr, M, Kd, GBK, tid);
    CP_COMMIT();

    // ldmatrix lane address components
    uint32_t aRow = (uint32_t)(lane & 15);
    uint32_t aKo  = (uint32_t)((lane >> 4) << 3);
    uint32_t bRow = (uint32_t)(lane & 7);
    uint32_t bNo  = (uint32_t)((lane >> 3) << 3);

    int s = 0;
    for (int i = 0; i < NB; i++) {
        CP_WAIT1();
        __syncthreads();

        if (i + 2 < NB) {
            int s2 = s + 2; if (s2 >= NSTG) s2 -= NSTG;
            fill_stage_h(sbase, s2, Aptr, Wptr, M, Kd, (i + 2) * GBK, tid);
            CP_COMMIT();
        }

        uint32_t sA = sbase + (uint32_t)s * STG_H * 2;
        uint32_t sB = sA + STG_A_H * 2;

        #pragma unroll
        for (int ks = 0; ks < GBK; ks += 16) {
            unsigned af[4][4], bf[4][2];
            #pragma unroll
            for (int mt = 0; mt < 4; mt++) {
                uint32_t addr = sA + (wm + mt * 16 + aRow) * 80 + (ks + aKo) * 2;
                asm volatile(
                    "ldmatrix.sync.aligned.m8n8.x4.shared.b16 {%0,%1,%2,%3}, [%4];"
                    : "=r"(af[mt][0]), "=r"(af[mt][1]), "=r"(af[mt][2]), "=r"(af[mt][3])
                    : "r"(addr));
            }
            #pragma unroll
            for (int kh = 0; kh < 2; kh++) {
                uint32_t addr = sB + (ks + kh * 8 + bRow) * 272 + (wn + bNo) * 2;
                unsigned r0, r1, r2, r3;
                asm volatile(
                    "ldmatrix.sync.aligned.m8n8.x4.trans.shared.b16 {%0,%1,%2,%3}, [%4];"
                    : "=r"(r0), "=r"(r1), "=r"(r2), "=r"(r3) : "r"(addr));
                bf[0][kh] = r0; bf[1][kh] = r1; bf[2][kh] = r2; bf[3][kh] = r3;
            }
            #pragma unroll
            for (int mt = 0; mt < 4; mt++)
                #pragma unroll
                for (int nt = 0; nt < 4; nt++) {
                    asm volatile(
                        "mma.sync.aligned.m16n8k16.row.col.f32.f16.f16.f32 "
                        "{%0,%1,%2,%3}, {%4,%5,%6,%7}, {%8,%9}, {%0,%1,%2,%3};"
                        : "+f"(acc[mt][nt][0]), "+f"(acc[mt][nt][1]),
                          "+f"(acc[mt][nt][2]), "+f"(acc[mt][nt][3])
                        : "r"(af[mt][0]), "r"(af[mt][1]), "r"(af[mt][2]), "r"(af[mt][3]),
                          "r"(bf[nt][0]), "r"(bf[nt][1]));
                }
        }
        if (++s >= NSTG) s -= NSTG;
    }

    // ---- Epilogue ----
    __half* Ch = (__half*)Cout;
    float*  Cf = (float*)Cout;
    #pragma unroll
    for (int mt = 0; mt < 4; mt++) {
        #pragma unroll
        for (int nt = 0; nt < 4; nt++) {
            int col = bn + wn + nt * 8 + 2 * th;
            float b0 = bias[col], b1 = bias[col + 1];
            #pragma unroll
            for (int hrow = 0; hrow < 2; hrow++) {
                int row = bm + wm + mt * 16 + g + hrow * 8;
                float v0 = acc[mt][nt][2 * hrow]     + b0;
                float v1 = acc[mt][nt][2 * hrow + 1] + b1;
                if (epi == 1) {
                    v0 = (v0 > 0.f) ? (v0 + 1.f) : expf(v0);
                    v1 = (v1 > 0.f) ? (v1 + 1.f) : expf(v1);
                } else if (epi == 2) {
                    v0 = 0.5f * v0 * (1.f + erff(v0 * 0.7071067811865475f));
                    v1 = 0.5f * v1 * (1.f + erff(v1 * 0.7071067811865475f));
                }
                if (epi == 3) {
                    const float2 r2 = *reinterpret_cast<const float2*>(
                        res + (size_t)row * M + col);
                    float2 o2 = make_float2(v0 + r2.x, v1 + r2.y);
                    *reinterpret_cast<float2*>(Cf + (size_t)row * M + col) = o2;
                } else {
                    *reinterpret_cast<__half2*>(Ch + (size_t)row * M + col) =
                        __floats2half2_rn(v0, v1);
                }
            }
        }
    }
}

// ---------------------------------------------------------------------------
// Zero a float buffer
// ---------------------------------------------------------------------------
__global__ void zero_kernel(float* p, int n) {
    int i = blockIdx.x * 256 + threadIdx.x;
    if (i < n) p[i] = 0.f;
}

// ---------------------------------------------------------------------------
// kv[bh][k][v] = sum_s keep_s * phi_k[s][k] * v[s][v]  ;  ksum[bh][k]
// ---------------------------------------------------------------------------
__global__ void kv_kernel(const __half* __restrict__ pk,
                          const __half* __restrict__ vv,
                          const unsigned char* __restrict__ mask)
{
    __shared__ float sp[8][CK];
    __shared__ float sv[8][CK];

    int bh = blockIdx.x;
    int chunk = blockIdx.y;
    int b = bh / CH, h = bh % CH;
    int t0 = chunk * (CT / 8);

    int tid = threadIdx.x;
    int r0 = (tid >> 4) << 2;
    int c0 = (tid & 15) << 2;

    float acc[4][4];
    #pragma unroll
    for (int i = 0; i < 4; i++)
        #pragma unroll
        for (int j = 0; j < 4; j++) acc[i][j] = 0.f;
    float ks = 0.f;

    for (int g = 0; g < 512; g += 8) {
        #pragma unroll
        for (int i = 0; i < 2; i++) {
            int e = tid + i * 256;
            int s = e >> 6, col = e & 63;
            int t = t0 + g + s;
            size_t rowm = (size_t)b * CT + t;
            float keep = mask[rowm] ? 0.f : 1.f;
            size_t idx = rowm * CD + (size_t)h * CK + col;
            sp[s][col] = __half2float(pk[idx]) * keep;
            sv[s][col] = __half2float(vv[idx]) * keep;
        }
        __syncthreads();
        #pragma unroll
        for (int s = 0; s < 8; s++) {
            float4 a  = *reinterpret_cast<const float4*>(&sp[s][r0]);
            float4 bb = *reinterpret_cast<const float4*>(&sv[s][c0]);
            float ar[4] = {a.x, a.y, a.z, a.w};
            float br[4] = {bb.x, bb.y, bb.z, bb.w};
            #pragma unroll
            for (int i = 0; i < 4; i++)
                #pragma unroll
                for (int j = 0; j < 4; j++)
                    acc[i][j] += ar[i] * br[j];
        }
        if (tid < CK) {
            #pragma unroll
            for (int s = 0; s < 8; s++) ks += sp[s][tid];
        }
        __syncthreads();
    }

    float* kvp = g_kv + (size_t)bh * CK * CK;
    #pragma unroll
    for (int i = 0; i < 4; i++)
        #pragma unroll
        for (int j = 0; j < 4; j++)
            atomicAdd(&kvp[(r0 + i) * CK + c0 + j], acc[i][j]);
    if (tid < CK) atomicAdd(&g_ksum[bh * CK + tid], ks);
}

// ---------------------------------------------------------------------------
// attn[t][c] = (phi_q[t] . kv[:,c]) / (phi_q[t] . ksum + eps)  (fp16 out)
// ---------------------------------------------------------------------------
__global__ void attn_kernel(const __half* __restrict__ pq,
                            __half* __restrict__ attn)
{
    __shared__ float skv[CK][CK];
    __shared__ float sks[CK];
    __shared__ float sq[8][CK];

    int bh = blockIdx.x, tb = blockIdx.y;
    int b = bh / CH, h = bh % CH;
    int tid = threadIdx.x;

    const float* kvp = g_kv + (size_t)bh * CK * CK;
    for (int i = tid; i < CK * CK; i += 256) skv[i >> 6][i & 63] = kvp[i];
    if (tid < CK) sks[tid] = g_ksum[bh * CK + tid];
    __syncthreads();

    int w = tid >> 5, l = tid & 31;
    for (int it = 0; it < 16; it++) {
        int t = tb * 128 + w * 16 + it;
        size_t rowp = ((size_t)b * CT + t) * CD + (size_t)h * CK;
        sq[w][l]      = __half2float(pq[rowp + l]);
        sq[w][l + 32] = __half2float(pq[rowp + l + 32]);
        __syncwarp();
        float n0 = 0.f, n1 = 0.f, den = DEN_EPS;
        #pragma unroll
        for (int k = 0; k < CK; k++) {
            float qv = sq[w][k];
            n0  += qv * skv[k][l];
            n1  += qv * skv[k][l + 32];
            den += qv * sks[k];
        }
        float inv = 1.f / den;
        attn[rowp + l]      = __float2half_rn(n0 * inv);
        attn[rowp + l + 32] = __float2half_rn(n1 * inv);
        __syncwarp();
    }
}

// ---------------------------------------------------------------------------
// Host launcher
// ---------------------------------------------------------------------------
extern "C" void kernel_launch(void* const* d_in, const int* in_sizes, int n_in,
                              void* d_out, int out_size)
{
    const float* x    = (const float*)d_in[0];
    const unsigned char* mask = (const unsigned char*)d_in[1];
    const float* Wq   = (const float*)d_in[2];
    const float* bq   = (const float*)d_in[3];
    const float* Wk   = (const float*)d_in[4];
    const float* bk   = (const float*)d_in[5];
    const float* Wv   = (const float*)d_in[6];
    const float* bv   = (const float*)d_in[7];
    const float* Wo   = (const float*)d_in[8];
    const float* bo   = (const float*)d_in[9];
    const float* ln1w = (const float*)d_in[10];
    const float* ln1b = (const float*)d_in[11];
    const float* ln2w = (const float*)d_in[12];
    const float* ln2b = (const float*)d_in[13];
    const float* W1   = (const float*)d_in[14];
    const float* b1   = (const float*)d_in[15];
    const float* W2   = (const float*)d_in[16];
    const float* b2   = (const float*)d_in[17];
    float* out = (float*)d_out;

    void *pxn, *pq, *pk, *pv, *pattn, *py, *ph, *pwh, *px2, *pkv, *pks;
    cudaGetSymbolAddress(&pxn, gh_xn);
    cudaGetSymbolAddress(&pq, gh_q);
    cudaGetSymbolAddress(&pk, gh_k);
    cudaGetSymbolAddress(&pv, gh_v);
    cudaGetSymbolAddress(&pattn, gh_attn);
    cudaGetSymbolAddress(&py, gh_y);
    cudaGetSymbolAddress(&ph, gh_h);
    cudaGetSymbolAddress(&pwh, gh_w);
    cudaGetSymbolAddress(&px2, g_x2);
    cudaGetSymbolAddress(&pkv, g_kv);
    cudaGetSymbolAddress(&pks, g_ksum);

    __half* xn  = (__half*)pxn;
    __half* qb  = (__half*)pq;
    __half* kb  = (__half*)pk;
    __half* vb  = (__half*)pv;
    __half* atb = (__half*)pattn;
    __half* yb  = (__half*)py;
    __half* hb  = (__half*)ph;
    __half* wh  = (__half*)pwh;
    float*  x2  = (float*)px2;
    float*  kvb = (float*)pkv;
    float*  ksb = (float*)pks;

    cudaFuncSetAttribute(gemm_h_kernel, cudaFuncAttributeMaxDynamicSharedMemorySize, GEMM_SMEM);

    // 0. Convert weights to fp16
    wconv_kernel<<<1024, 256>>>(Wq, wh + WT_Q, 1024*1024/4);
    wconv_kernel<<<1024, 256>>>(Wk, wh + WT_K, 1024*1024/4);
    wconv_kernel<<<1024, 256>>>(Wv, wh + WT_V, 1024*1024/4);
    wconv_kernel<<<1024, 256>>>(Wo, wh + WT_O, 1024*1024/4);
    wconv_kernel<<<4096, 256>>>(W1, wh + WT_1, 4*1024*1024/4);
    wconv_kernel<<<4096, 256>>>(W2, wh + WT_2, 4*1024*1024/4);

    // 1. LN1 -> fp16
    ln_kernel<<<CN, 256>>>(x, ln1w, ln1b, xn);

    // 2-4. QKV projections (phi fused into Q,K), fp16 out
    dim3 gD(CD / GBN, CN / GBM);
    gemm_h_kernel<<<gD, 256, GEMM_SMEM>>>(xn, wh + WT_Q, bq, nullptr, qb, CD, CD, 1);
    gemm_h_kernel<<<gD, 256, GEMM_SMEM>>>(xn, wh + WT_K, bk, nullptr, kb, CD, CD, 1);
    gemm_h_kernel<<<gD, 256, GEMM_SMEM>>>(xn, wh + WT_V, bv, nullptr, vb, CD, CD, 0);

    // 5. zero kv/ksum accumulators
    zero_kernel<<<(CB*CH*CK*CK + 255) / 256, 256>>>(kvb, CB*CH*CK*CK);
    zero_kernel<<<(CB*CH*CK + 255) / 256, 256>>>(ksb, CB*CH*CK);

    // 6. kv + ksum reduction (masked)
    kv_kernel<<<dim3(CB*CH, 8), 256>>>(kb, vb, mask);

    // 7. numerator / denominator -> fp16
    attn_kernel<<<dim3(CB*CH, CT / 128), 256>>>(qb, atb);

    // 8. O projection + residual -> fp32 x2
    gemm_h_kernel<<<gD, 256, GEMM_SMEM>>>(atb, wh + WT_O, bo, x, x2, CD, CD, 3);

    // 9. LN2 -> fp16
    ln_kernel<<<CN, 256>>>(x2, ln2w, ln2b, yb);

    // 10. FFN1 + exact GELU -> fp16
    dim3 gF(CF / GBN, CN / GBM);
    gemm_h_kernel<<<gF, 256, GEMM_SMEM>>>(yb, wh + WT_1, b1, nullptr, hb, CF, CD, 2);

    // 11. FFN2 + residual -> fp32 output
    gemm_h_kernel<<<gD, 256, GEMM_SMEM>>>(hb, wh + WT_2, b2, x2, out, CD, CF, 3);
}

// round 6
// speedup vs baseline: 5.6993x; 1.0344x over previous
#include <cuda_runtime.h>
#include <cuda_fp16.h>
#include <math.h>
#include <stdint.h>

// Problem constants
#define CB 4
#define CT 4096
#define CD 1024
#define CH 16
#define CK 64
#define CF 4096
#define CN (CB*CT)          // 16384 tokens

#define LN_EPS  1e-5f
#define DEN_EPS 1e-6f

// ---------------------------------------------------------------------------
// Scratch (allocation-free: __device__ globals)
// ---------------------------------------------------------------------------
__device__ __half gh_xn  [(size_t)CN*CD];
__device__ __half gh_q   [(size_t)CN*CD];
__device__ __half gh_k   [(size_t)CN*CD];
__device__ __half gh_v   [(size_t)CN*CD];
__device__ __half gh_attn[(size_t)CN*CD];
__device__ __half gh_y   [(size_t)CN*CD];
__device__ __half gh_h   [(size_t)CN*CF];
__device__ __half gh_w   [12u*1024u*1024u];   // fp16 weights (contiguous)
__device__ float  g_x2   [(size_t)CN*CD];
__device__ float  g_kv   [CB*CH*CK*CK];
__device__ float  g_ksum [CB*CH*CK];

// Offsets into gh_w (halves)
#define WT_Q 0u
#define WT_K (1u*1024u*1024u)
#define WT_V (2u*1024u*1024u)
#define WT_O (3u*1024u*1024u)
#define WT_1 (4u*1024u*1024u)
#define WT_2 (8u*1024u*1024u)

// ---------------------------------------------------------------------------
// Helpers
// ---------------------------------------------------------------------------
__device__ __forceinline__ uint32_t s2u(const void* p) {
    uint32_t a;
    asm("{ .reg .u64 t; cvta.to.shared.u64 t, %1; cvt.u32.u64 %0, t; }" : "=r"(a) : "l"(p));
    return a;
}
__device__ __forceinline__ void cpa16(uint32_t d, const void* s) {
    asm volatile("cp.async.cg.shared.global [%0], [%1], 16;" :: "r"(d), "l"(s));
}
#define CP_COMMIT() asm volatile("cp.async.commit_group;" ::: "memory")
#define CP_WAIT1()  asm volatile("cp.async.wait_group 1;" ::: "memory")

// ---------------------------------------------------------------------------
// LayerNorm: one block per row (1024 elems), 256 threads x float4 -> fp16 out
// ---------------------------------------------------------------------------
__device__ __forceinline__ float block_sum_256(float v, float* red) {
    #pragma unroll
    for (int o = 16; o > 0; o >>= 1) v += __shfl_xor_sync(0xffffffffu, v, o);
    if ((threadIdx.x & 31) == 0) red[threadIdx.x >> 5] = v;
    __syncthreads();
    if (threadIdx.x < 32) {
        float t = (threadIdx.x < 8) ? red[threadIdx.x] : 0.f;
        #pragma unroll
        for (int o = 4; o > 0; o >>= 1) t += __shfl_xor_sync(0xffffffffu, t, o);
        if (threadIdx.x == 0) red[8] = t;
    }
    __syncthreads();
    return red[8];
}

__global__ void ln_kernel(const float* __restrict__ x,
                          const float* __restrict__ w,
                          const float* __restrict__ b,
                          __half* __restrict__ y)
{
    __shared__ float red[9];
    int row = blockIdx.x;
    int tid = threadIdx.x;
    const float4* xr = reinterpret_cast<const float4*>(x + (size_t)row * CD);
    float4 v = xr[tid];

    float s = v.x + v.y + v.z + v.w;
    float mean = block_sum_256(s, red) * (1.f / CD);

    float dx = v.x - mean, dy = v.y - mean, dz = v.z - mean, dw = v.w - mean;
    float s2 = dx*dx + dy*dy + dz*dz + dw*dw;
    float var = block_sum_256(s2, red) * (1.f / CD);
    float rs = rsqrtf(var + LN_EPS);

    float4 wv = reinterpret_cast<const float4*>(w)[tid];
    float4 bv = reinterpret_cast<const float4*>(b)[tid];
    __half2 h0 = __floats2half2_rn(dx * rs * wv.x + bv.x, dy * rs * wv.y + bv.y);
    __half2 h1 = __floats2half2_rn(dz * rs * wv.z + bv.z, dw * rs * wv.w + bv.w);
    __half2* yp = reinterpret_cast<__half2*>(y + (size_t)row * CD + tid * 4);
    yp[0] = h0; yp[1] = h1;
}

// ---------------------------------------------------------------------------
// Merged weight convert float -> fp16 (all 6 weights, contiguous dst)
// i indexes float4; segments: Q,K,V,O (256K f4 each), W1 (1M f4), W2 (1M f4)
// ---------------------------------------------------------------------------
__global__ void wconv_all_kernel(const float* __restrict__ Wq, const float* __restrict__ Wk,
                                 const float* __restrict__ Wv, const float* __restrict__ Wo,
                                 const float* __restrict__ W1, const float* __restrict__ W2,
                                 __half* __restrict__ dst)
{
    int i = blockIdx.x * 256 + threadIdx.x;      // 0 .. 3M-1 float4
    const float* src;
    int local;
    if (i < (1 << 20)) {                          // Q,K,V,O region: 4 x 256K
        int seg = i >> 18, off = i & ((1 << 18) - 1);
        src = (seg == 0) ? Wq : (seg == 1) ? Wk : (seg == 2) ? Wv : Wo;
        local = off;
    } else if (i < (2 << 20)) {
        src = W1; local = i - (1 << 20);
    } else {
        src = W2; local = i - (2 << 20);
    }
    float4 v = reinterpret_cast<const float4*>(src)[local];
    __half2* d = reinterpret_cast<__half2*>(dst + (size_t)i * 4);
    d[0] = __floats2half2_rn(v.x, v.y);
    d[1] = __floats2half2_rn(v.z, v.w);
}

// ---------------------------------------------------------------------------
// fp16 tensor-core GEMM, 3-stage cp.async pipeline, ldmatrix fragments.
// C[N,M] = A[N,Kd] @ W[Kd,M] + bias (+ epilogue), fp32 accumulate.
// 128x128x64 tile, 256 threads = 8 warps (2M x 4N), warp tile 64x32,
// 4x4 m16n8k16 fragments per warp per 16-wide k-step (4 steps per block).
// Smem rows: A padded to 144B (72 halves), B to 272B (136 halves).
// epi: 0=none->h, 1=phi(elu+1)->h, 2=gelu->h, 3=+res(f32)->f32
// ---------------------------------------------------------------------------
#define GBM 128
#define GBN 128
#define GBK 64
#define ASTRH 72
#define BSTRH 136
#define STG_A_H (GBM*ASTRH)        // 9216 halves
#define STG_B_H (GBK*BSTRH)        // 8704 halves
#define STG_H   (STG_A_H+STG_B_H)  // 17920 halves
#define NSTG 3
#define GEMM_SMEM (NSTG*STG_H*2)   // 107520 bytes

__device__ __forceinline__ void fill_stage_h(uint32_t sbase, int s,
    const __half* __restrict__ Ab, const __half* __restrict__ Wb,
    int M, int Kd, int k0, int tid)
{
    uint32_t sA = sbase + (uint32_t)s * STG_H * 2;
    uint32_t sB = sA + STG_A_H * 2;
    const __half* ap = Ab + k0;
    const __half* wp = Wb + (size_t)k0 * M;
    #pragma unroll
    for (int j = 0; j < 4; j++) {
        int e = tid + j * 256;          // 0..1023
        int r = e >> 3, c = e & 7;      // A: 128 rows x 8 16B-chunks
        cpa16(sA + r * 144 + c * 16, ap + (size_t)r * Kd + c * 8);
    }
    #pragma unroll
    for (int j = 0; j < 4; j++) {
        int e = tid + j * 256;
        int r = e >> 4, c = e & 15;     // B: 64 rows x 16 16B-chunks
        cpa16(sB + r * 272 + c * 16, wp + (size_t)r * M + c * 8);
    }
}

__global__ __launch_bounds__(256, 2) void gemm_h_kernel(
    const __half* __restrict__ A, const __half* __restrict__ W,
    const float* __restrict__ bias, const float* __restrict__ res,
    void* __restrict__ Cout, int M, int Kd, int epi)
{
    extern __shared__ __half smem[];
    uint32_t sbase = s2u(smem);

    int tid  = threadIdx.x;
    int warp = tid >> 5;
    int lane = tid & 31;
    int g  = lane >> 2;
    int th = lane & 3;
    int wm = (warp & 1) * 64;
    int wn = (warp >> 1) * 32;

    int bm = blockIdx.y * GBM;
    int bn = blockIdx.x * GBN;

    const __half* Aptr = A + (size_t)bm * Kd;
    const __half* Wptr = W + bn;

    float acc[4][4][4];
    #pragma unroll
    for (int i = 0; i < 4; i++)
        #pragma unroll
        for (int j = 0; j < 4; j++)
            #pragma unroll
            for (int c = 0; c < 4; c++) acc[i][j][c] = 0.f;

    int NB = Kd >> 6;

    fill_stage_h(sbase, 0, Aptr, Wptr, M, Kd, 0, tid);
    CP_COMMIT();
    fill_stage_h(sbase, 1, Aptr, Wptr, M, Kd, GBK, tid);
    CP_COMMIT();

    uint32_t aRow = (uint32_t)(lane & 15);
    uint32_t aKo  = (uint32_t)((lane >> 4) << 3);
    uint32_t bRow = (uint32_t)(lane & 7);
    uint32_t bNo  = (uint32_t)((lane >> 3) << 3);

    int s = 0;
    for (int i = 0; i < NB; i++) {
        CP_WAIT1();
        __syncthreads();

        if (i + 2 < NB) {
            int s2 = s + 2; if (s2 >= NSTG) s2 -= NSTG;
            fill_stage_h(sbase, s2, Aptr, Wptr, M, Kd, (i + 2) * GBK, tid);
            CP_COMMIT();
        }

        uint32_t sA = sbase + (uint32_t)s * STG_H * 2;
        uint32_t sB = sA + STG_A_H * 2;

        #pragma unroll
        for (int ks = 0; ks < GBK; ks += 16) {
            unsigned af[4][4], bf[4][2];
            #pragma unroll
            for (int mt = 0; mt < 4; mt++) {
                uint32_t addr = sA + (wm + mt * 16 + aRow) * 144 + (ks + aKo) * 2;
                asm volatile(
                    "ldmatrix.sync.aligned.m8n8.x4.shared.b16 {%0,%1,%2,%3}, [%4];"
                    : "=r"(af[mt][0]), "=r"(af[mt][1]), "=r"(af[mt][2]), "=r"(af[mt][3])
                    : "r"(addr));
            }
            #pragma unroll
            for (int kh = 0; kh < 2; kh++) {
                uint32_t addr = sB + (ks + kh * 8 + bRow) * 272 + (wn + bNo) * 2;
                unsigned r0, r1, r2, r3;
                asm volatile(
                    "ldmatrix.sync.aligned.m8n8.x4.trans.shared.b16 {%0,%1,%2,%3}, [%4];"
                    : "=r"(r0), "=r"(r1), "=r"(r2), "=r"(r3) : "r"(addr));
                bf[0][kh] = r0; bf[1][kh] = r1; bf[2][kh] = r2; bf[3][kh] = r3;
            }
            #pragma unroll
            for (int mt = 0; mt < 4; mt++)
                #pragma unroll
                for (int nt = 0; nt < 4; nt++) {
                    asm volatile(
                        "mma.sync.aligned.m16n8k16.row.col.f32.f16.f16.f32 "
                        "{%0,%1,%2,%3}, {%4,%5,%6,%7}, {%8,%9}, {%0,%1,%2,%3};"
                        : "+f"(acc[mt][nt][0]), "+f"(acc[mt][nt][1]),
                          "+f"(acc[mt][nt][2]), "+f"(acc[mt][nt][3])
                        : "r"(af[mt][0]), "r"(af[mt][1]), "r"(af[mt][2]), "r"(af[mt][3]),
                          "r"(bf[nt][0]), "r"(bf[nt][1]));
                }
        }
        if (++s >= NSTG) s -= NSTG;
    }

    // ---- Epilogue ----
    __half* Ch = (__half*)Cout;
    float*  Cf = (float*)Cout;
    #pragma unroll
    for (int mt = 0; mt < 4; mt++) {
        #pragma unroll
        for (int nt = 0; nt < 4; nt++) {
            int col = bn + wn + nt * 8 + 2 * th;
            float b0 = bias[col], b1 = bias[col + 1];
            #pragma unroll
            for (int hrow = 0; hrow < 2; hrow++) {
                int row = bm + wm + mt * 16 + g + hrow * 8;
                float v0 = acc[mt][nt][2 * hrow]     + b0;
                float v1 = acc[mt][nt][2 * hrow + 1] + b1;
                if (epi == 1) {
                    v0 = (v0 > 0.f) ? (v0 + 1.f) : expf(v0);
                    v1 = (v1 > 0.f) ? (v1 + 1.f) : expf(v1);
                } else if (epi == 2) {
                    v0 = 0.5f * v0 * (1.f + erff(v0 * 0.7071067811865475f));
                    v1 = 0.5f * v1 * (1.f + erff(v1 * 0.7071067811865475f));
                }
                if (epi == 3) {
                    const float2 r2 = *reinterpret_cast<const float2*>(
                        res + (size_t)row * M + col);
                    float2 o2 = make_float2(v0 + r2.x, v1 + r2.y);
                    *reinterpret_cast<float2*>(Cf + (size_t)row * M + col) = o2;
                } else {
                    *reinterpret_cast<__half2*>(Ch + (size_t)row * M + col) =
                        __floats2half2_rn(v0, v1);
                }
            }
        }
    }
}

// ---------------------------------------------------------------------------
// Zero a float buffer
// ---------------------------------------------------------------------------
__global__ void zero_kernel(float* p, int n) {
    int i = blockIdx.x * 256 + threadIdx.x;
    if (i < n) p[i] = 0.f;
}

// ---------------------------------------------------------------------------
// kv[bh][k][v] = sum_s keep_s * phi_k[s][k] * v[s][v]  ;  ksum[bh][k]
// ---------------------------------------------------------------------------
__global__ void kv_kernel(const __half* __restrict__ pk,
                          const __half* __restrict__ vv,
                          const unsigned char* __restrict__ mask)
{
    __shared__ float sp[8][CK];
    __shared__ float sv[8][CK];

    int bh = blockIdx.x;
    int chunk = blockIdx.y;
    int b = bh / CH, h = bh % CH;
    int t0 = chunk * (CT / 8);

    int tid = threadIdx.x;
    int r0 = (tid >> 4) << 2;
    int c0 = (tid & 15) << 2;

    float acc[4][4];
    #pragma unroll
    for (int i = 0; i < 4; i++)
        #pragma unroll
        for (int j = 0; j < 4; j++) acc[i][j] = 0.f;
    float ks = 0.f;

    for (int g = 0; g < 512; g += 8) {
        #pragma unroll
        for (int i = 0; i < 2; i++) {
            int e = tid + i * 256;
            int s = e >> 6, col = e & 63;
            int t = t0 + g + s;
            size_t rowm = (size_t)b * CT + t;
            float keep = mask[rowm] ? 0.f : 1.f;
            size_t idx = rowm * CD + (size_t)h * CK + col;
            sp[s][col] = __half2float(pk[idx]) * keep;
            sv[s][col] = __half2float(vv[idx]) * keep;
        }
        __syncthreads();
        #pragma unroll
        for (int s = 0; s < 8; s++) {
            float4 a  = *reinterpret_cast<const float4*>(&sp[s][r0]);
            float4 bb = *reinterpret_cast<const float4*>(&sv[s][c0]);
            float ar[4] = {a.x, a.y, a.z, a.w};
            float br[4] = {bb.x, bb.y, bb.z, bb.w};
            #pragma unroll
            for (int i = 0; i < 4; i++)
                #pragma unroll
                for (int j = 0; j < 4; j++)
                    acc[i][j] += ar[i] * br[j];
        }
        if (tid < CK) {
            #pragma unroll
            for (int s = 0; s < 8; s++) ks += sp[s][tid];
        }
        __syncthreads();
    }

    float* kvp = g_kv + (size_t)bh * CK * CK;
    #pragma unroll
    for (int i = 0; i < 4; i++)
        #pragma unroll
        for (int j = 0; j < 4; j++)
            atomicAdd(&kvp[(r0 + i) * CK + c0 + j], acc[i][j]);
    if (tid < CK) atomicAdd(&g_ksum[bh * CK + tid], ks);
}

// ---------------------------------------------------------------------------
// attn[t][c] = (phi_q[t] . kv[:,c]) / (phi_q[t] . ksum + eps)  (fp16 out)
// ---------------------------------------------------------------------------
__global__ void attn_kernel(const __half* __restrict__ pq,
                            __half* __restrict__ attn)
{
    __shared__ float skv[CK][CK];
    __shared__ float sks[CK];
    __shared__ float sq[8][CK];

    int bh = blockIdx.x, tb = blockIdx.y;
    int b = bh / CH, h = bh % CH;
    int tid = threadIdx.x;

    const float* kvp = g_kv + (size_t)bh * CK * CK;
    for (int i = tid; i < CK * CK; i += 256) skv[i >> 6][i & 63] = kvp[i];
    if (tid < CK) sks[tid] = g_ksum[bh * CK + tid];
    __syncthreads();

    int w = tid >> 5, l = tid & 31;
    for (int it = 0; it < 16; it++) {
        int t = tb * 128 + w * 16 + it;
        size_t rowp = ((size_t)b * CT + t) * CD + (size_t)h * CK;
        sq[w][l]      = __half2float(pq[rowp + l]);
        sq[w][l + 32] = __half2float(pq[rowp + l + 32]);
        __syncwarp();
        float n0 = 0.f, n1 = 0.f, den = DEN_EPS;
        #pragma unroll
        for (int k = 0; k < CK; k++) {
            float qv = sq[w][k];
            n0  += qv * skv[k][l];
            n1  += qv * skv[k][l + 32];
            den += qv * sks[k];
        }
        float inv = 1.f / den;
        attn[rowp + l]      = __float2half_rn(n0 * inv);
        attn[rowp + l + 32] = __float2half_rn(n1 * inv);
        __syncwarp();
    }
}

// ---------------------------------------------------------------------------
// Host launcher
// ---------------------------------------------------------------------------
extern "C" void kernel_launch(void* const* d_in, const int* in_sizes, int n_in,
                              void* d_out, int out_size)
{
    const float* x    = (const float*)d_in[0];
    const unsigned char* mask = (const unsigned char*)d_in[1];
    const float* Wq   = (const float*)d_in[2];
    const float* bq   = (const float*)d_in[3];
    const float* Wk   = (const float*)d_in[4];
    const float* bk   = (const float*)d_in[5];
    const float* Wv   = (const float*)d_in[6];
    const float* bv   = (const float*)d_in[7];
    const float* Wo   = (const float*)d_in[8];
    const float* bo   = (const float*)d_in[9];
    const float* ln1w = (const float*)d_in[10];
    const float* ln1b = (const float*)d_in[11];
    const float* ln2w = (const float*)d_in[12];
    const float* ln2b = (const float*)d_in[13];
    const float* W1   = (const float*)d_in[14];
    const float* b1   = (const float*)d_in[15];
    const float* W2   = (const float*)d_in[16];
    const float* b2   = (const float*)d_in[17];
    float* out = (float*)d_out;

    void *pxn, *pq, *pk, *pv, *pattn, *py, *ph, *pwh, *px2, *pkv, *pks;
    cudaGetSymbolAddress(&pxn, gh_xn);
    cudaGetSymbolAddress(&pq, gh_q);
    cudaGetSymbolAddress(&pk, gh_k);
    cudaGetSymbolAddress(&pv, gh_v);
    cudaGetSymbolAddress(&pattn, gh_attn);
    cudaGetSymbolAddress(&py, gh_y);
    cudaGetSymbolAddress(&ph, gh_h);
    cudaGetSymbolAddress(&pwh, gh_w);
    cudaGetSymbolAddress(&px2, g_x2);
    cudaGetSymbolAddress(&pkv, g_kv);
    cudaGetSymbolAddress(&pks, g_ksum);

    __half* xn  = (__half*)pxn;
    __half* qb  = (__half*)pq;
    __half* kb  = (__half*)pk;
    __half* vb  = (__half*)pv;
    __half* atb = (__half*)pattn;
    __half* yb  = (__half*)py;
    __half* hb  = (__half*)ph;
    __half* wh  = (__half*)pwh;
    float*  x2  = (float*)px2;
    float*  kvb = (float*)pkv;
    float*  ksb = (float*)pks;

    cudaFuncSetAttribute(gemm_h_kernel, cudaFuncAttributeMaxDynamicSharedMemorySize, GEMM_SMEM);

    // 0. Convert all weights to fp16 in one launch (3M float4 total)
    wconv_all_kernel<<<12288, 256>>>(Wq, Wk, Wv, Wo, W1, W2, wh);

    // 1. LN1 -> fp16
    ln_kernel<<<CN, 256>>>(x, ln1w, ln1b, xn);

    // 2-4. QKV projections (phi fused into Q,K), fp16 out
    dim3 gD(CD / GBN, CN / GBM);
    gemm_h_kernel<<<gD, 256, GEMM_SMEM>>>(xn, wh + WT_Q, bq, nullptr, qb, CD, CD, 1);
    gemm_h_kernel<<<gD, 256, GEMM_SMEM>>>(xn, wh + WT_K, bk, nullptr, kb, CD, CD, 1);
    gemm_h_kernel<<<gD, 256, GEMM_SMEM>>>(xn, wh + WT_V, bv, nullptr, vb, CD, CD, 0);

    // 5. zero kv/ksum accumulators
    zero_kernel<<<(CB*CH*CK*CK + 255) / 256, 256>>>(kvb, CB*CH*CK*CK);
    zero_kernel<<<(CB*CH*CK + 255) / 256, 256>>>(ksb, CB*CH*CK);

    // 6. kv + ksum reduction (masked)
    kv_kernel<<<dim3(CB*CH, 8), 256>>>(kb, vb, mask);

    // 7. numerator / denominator -> fp16
    attn_kernel<<<dim3(CB*CH, CT / 128), 256>>>(qb, atb);

    // 8. O projection + residual -> fp32 x2
    gemm_h_kernel<<<gD, 256, GEMM_SMEM>>>(atb, wh + WT_O, bo, x, x2, CD, CD, 3);

    // 9. LN2 -> fp16
    ln_kernel<<<CN, 256>>>(x2, ln2w, ln2b, yb);

    // 10. FFN1 + exact GELU -> fp16
    dim3 gF(CF / GBN, CN / GBM);
    gemm_h_kernel<<<gF, 256, GEMM_SMEM>>>(yb, wh + WT_1, b1, nullptr, hb, CF, CD, 2);

    // 11. FFN2 + residual -> fp32 output
    gemm_h_kernel<<<gD, 256, GEMM_SMEM>>>(hb, wh + WT_2, b2, x2, out, CD, CF, 3);
}